// round 2
// baseline (speedup 1.0000x reference)
#include <cuda_runtime.h>
#include <math.h>

#define NPROB  64
#define NRR    8
#define NK     500
#define HDIM   256
#define NHEADS 8
#define HD     32
#define BATCH  512   // NPROB*NRR

// ---------------- scratch (no allocations allowed) ----------------
__device__ float g_gl[BATCH * HDIM];     // glimpse (concat heads), [b][H]
__device__ float g_qm[BATCH * HDIM];     // glimpse @ nn_O
__device__ float g_logit[BATCH * NK];    // masked logits (-1e30 sentinel)
__device__ int   g_mask_mode;            // 0=u8,1=i32,2=f32,3=bf16
__device__ unsigned char g_mask[BATCH * NK];

// accurate tanh: 1 - 2/(exp(2x)+1); saturates correctly at +-inf
__device__ __forceinline__ float tanh_acc(float x) {
    float e = __expf(2.0f * x);
    return 1.0f - __fdividef(2.0f, e + 1.0f);
}
__device__ __forceinline__ float sigmoidf_(float x) {
    return 1.0f / (1.0f + __expf(-x));
}

// =================================================================
// Kernel 0a: detect mask dtype from raw bits (first 64000 words are
// in-bounds for every candidate dtype: u8=256000B, bf16=512000B,
// i32/f32=1024000B).
// =================================================================
__global__ void detect_mask_kernel(const unsigned int* __restrict__ mraw)
{
    __shared__ int s_i32, s_f32, s_bf16;
    const int t = threadIdx.x;
    if (t == 0) { s_i32 = 1; s_f32 = 1; s_bf16 = 1; }
    __syncthreads();
    int ok_i32 = 1, ok_f32 = 1, ok_bf16 = 1;
    for (int i = t; i < 64000; i += blockDim.x) {
        unsigned int w = mraw[i];
        ok_i32  &= (w <= 1u);
        ok_f32  &= (w == 0u || w == 0x3F800000u);
        unsigned int lo = w & 0xFFFFu, hi = w >> 16;
        ok_bf16 &= (lo == 0u || lo == 0x3F80u) && (hi == 0u || hi == 0x3F80u);
    }
    if (!ok_i32)  atomicAnd(&s_i32, 0);
    if (!ok_f32)  atomicAnd(&s_f32, 0);
    if (!ok_bf16) atomicAnd(&s_bf16, 0);
    __syncthreads();
    if (t == 0) {
        int mode = 0;                 // default: u8 bytes
        if (s_i32) mode = 1;
        else if (s_f32) mode = 2;
        else if (s_bf16) mode = 3;
        g_mask_mode = mode;
    }
}

// =================================================================
// Kernel 0b: normalize mask to bytes in g_mask
// =================================================================
__global__ void normalize_mask_kernel(const void* __restrict__ mraw)
{
    const int idx = blockIdx.x * blockDim.x + threadIdx.x;
    if (idx >= BATCH * NK) return;
    const int mode = g_mask_mode;
    unsigned char v;
    if (mode == 1)      v = (((const int*)mraw)[idx] != 0);
    else if (mode == 2) v = (((const unsigned int*)mraw)[idx] != 0u);
    else if (mode == 3) v = (((const unsigned short*)mraw)[idx] != 0u);
    else                v = (((const unsigned char*)mraw)[idx] != 0u);
    g_mask[idx] = v;
}

// =================================================================
// Kernel 1: LSTM cell.  gates = [query|state1] @ [W_ih|W_hh]^T + biases
// =================================================================
__global__ __launch_bounds__(256)
void lstm_kernel(const float* __restrict__ query, const float* __restrict__ state1,
                 const float* __restrict__ state2,
                 const float* __restrict__ W_ih, const float* __restrict__ W_hh,
                 const float* __restrict__ b_ih, const float* __restrict__ b_hh,
                 float* __restrict__ out_h, float* __restrict__ out_c)
{
    __shared__ float A_s[32][33];
    __shared__ float W_s[4][32][33];
    const int t  = threadIdx.x;
    const int tx = t & 31, ty = t >> 5;      // ty 0..7
    const int b0 = blockIdx.x * 32, j0 = blockIdx.y * 32;
    const int lrow = t >> 3, lk = (t & 7) * 4;

    float acc[4][4];
#pragma unroll
    for (int i = 0; i < 4; i++)
#pragma unroll
        for (int j = 0; j < 4; j++) acc[i][j] = 0.0f;

    for (int k0 = 0; k0 < 512; k0 += 32) {
        const float* Asrc = (k0 < 256) ? (query + k0) : (state1 + (k0 - 256));
        const float* Wsrc = (k0 < 256) ? (W_ih + k0)  : (W_hh  + (k0 - 256));
        float4 av = *(const float4*)&Asrc[(b0 + lrow) * 256 + lk];
        A_s[lrow][lk + 0] = av.x; A_s[lrow][lk + 1] = av.y;
        A_s[lrow][lk + 2] = av.z; A_s[lrow][lk + 3] = av.w;
#pragma unroll
        for (int gg = 0; gg < 4; gg++) {
            float4 wv = *(const float4*)&Wsrc[(gg * 256 + j0 + lrow) * 256 + lk];
            W_s[gg][lrow][lk + 0] = wv.x; W_s[gg][lrow][lk + 1] = wv.y;
            W_s[gg][lrow][lk + 2] = wv.z; W_s[gg][lrow][lk + 3] = wv.w;
        }
        __syncthreads();
#pragma unroll
        for (int kk = 0; kk < 32; kk++) {
            float a0 = A_s[ty][kk], a1 = A_s[ty + 8][kk];
            float a2 = A_s[ty + 16][kk], a3 = A_s[ty + 24][kk];
            float w0 = W_s[0][tx][kk], w1 = W_s[1][tx][kk];
            float w2 = W_s[2][tx][kk], w3 = W_s[3][tx][kk];
            acc[0][0] += a0 * w0; acc[0][1] += a0 * w1; acc[0][2] += a0 * w2; acc[0][3] += a0 * w3;
            acc[1][0] += a1 * w0; acc[1][1] += a1 * w1; acc[1][2] += a1 * w2; acc[1][3] += a1 * w3;
            acc[2][0] += a2 * w0; acc[2][1] += a2 * w1; acc[2][2] += a2 * w2; acc[2][3] += a2 * w3;
            acc[3][0] += a3 * w0; acc[3][1] += a3 * w1; acc[3][2] += a3 * w2; acc[3][3] += a3 * w3;
        }
        __syncthreads();
    }

    const int j = j0 + tx;
    const float bias0 = b_ih[j]       + b_hh[j];
    const float bias1 = b_ih[256 + j] + b_hh[256 + j];
    const float bias2 = b_ih[512 + j] + b_hh[512 + j];
    const float bias3 = b_ih[768 + j] + b_hh[768 + j];
#pragma unroll
    for (int ri = 0; ri < 4; ri++) {
        const int b = b0 + ty + 8 * ri;
        float ig = sigmoidf_(acc[ri][0] + bias0);
        float fg = sigmoidf_(acc[ri][1] + bias1);
        float gg = tanhf(acc[ri][2] + bias2);
        float og = sigmoidf_(acc[ri][3] + bias3);
        float c  = fg * state2[b * 256 + j] + ig * gg;
        float h  = og * tanhf(c);
        out_h[b * 256 + j] = h;
        out_c[b * 256 + j] = c;
    }
}

// =================================================================
// Kernel 2: glimpse attention.  One block per (head a, problem p).
// =================================================================
__global__ __launch_bounds__(256)
void glimpse_kernel(const float* __restrict__ h_in, const float* __restrict__ Kt,
                    const float* __restrict__ Vt,
                    const float* __restrict__ nn_Q)
{
    __shared__ float q_s[8 * 256];
    __shared__ __align__(16) float Q_s[8 * 32];
    __shared__ float S_s[8 * 512];
    __shared__ float K_s[64 * 33];
    __shared__ float inv_s[8];

    const int t = threadIdx.x;
    const int a = blockIdx.x >> 6;
    const int p = blockIdx.x & 63;
    const int kb = (a * 64 + p) * NK * HD;

    // 1. stage q (h rows p*8..p*8+7 are contiguous)
    for (int i = t; i < 2048; i += 256) q_s[i] = h_in[p * 8 * 256 + i];
    __syncthreads();

    // 2. Q = q @ nn_Q[a], scaled by 1/sqrt(HD)
    {
        const int q = t >> 5, d = t & 31;
        const float* qn = nn_Q + a * 256 * 32 + d;
        const float* qr = q_s + q * 256;
        float s0 = 0, s1 = 0, s2 = 0, s3 = 0;
#pragma unroll 4
        for (int hh = 0; hh < 256; hh += 4) {
            s0 += qr[hh + 0] * qn[(hh + 0) * 32];
            s1 += qr[hh + 1] * qn[(hh + 1) * 32];
            s2 += qr[hh + 2] * qn[(hh + 2) * 32];
            s3 += qr[hh + 3] * qn[(hh + 3) * 32];
        }
        Q_s[q * 32 + d] = (s0 + s1 + s2 + s3) * 0.17677669529663687f;
    }
    __syncthreads();

    // 3. S = Q K^T (masked), staged K chunks of 64 rows
    const int kloc = t & 63, qp = t >> 6;
    const int q0 = qp * 2, q1 = q0 + 1;
    for (int c0 = 0; c0 < NK; c0 += 64) {
        for (int i = t; i < 2048; i += 256) {
            int row = i >> 5, d = i & 31;
            K_s[row * 33 + d] = (c0 + row < NK) ? Kt[kb + (c0 + row) * 32 + d] : 0.0f;
        }
        __syncthreads();
        int kg = c0 + kloc;
        if (kg < NK) {
            float acc0 = 0, acc1 = 0;
            const float4* Qs4 = (const float4*)Q_s;
#pragma unroll
            for (int d4 = 0; d4 < 8; d4++) {
                float4 qa = Qs4[q0 * 8 + d4];
                float4 qb = Qs4[q1 * 8 + d4];
                int kbs = kloc * 33 + d4 * 4;
                float k0v = K_s[kbs], k1v = K_s[kbs + 1];
                float k2v = K_s[kbs + 2], k3v = K_s[kbs + 3];
                acc0 += k0v * qa.x + k1v * qa.y + k2v * qa.z + k3v * qa.w;
                acc1 += k0v * qb.x + k1v * qb.y + k2v * qb.z + k3v * qb.w;
            }
            S_s[q0 * 512 + kg] = g_mask[(p * 8 + q0) * NK + kg] ? -1e30f : acc0;
            S_s[q1 * 512 + kg] = g_mask[(p * 8 + q1) * NK + kg] ? -1e30f : acc1;
        }
        __syncthreads();
    }

    // 4. softmax per q (warp w -> q = w), store un-normalized exp + 1/sum
    {
        const int w = t >> 5, l = t & 31;
        float mx = -1e30f;
        for (int k = l; k < NK; k += 32) mx = fmaxf(mx, S_s[w * 512 + k]);
#pragma unroll
        for (int o = 16; o >= 1; o >>= 1) mx = fmaxf(mx, __shfl_xor_sync(0xffffffffu, mx, o));
        float sm = 0;
        for (int k = l; k < NK; k += 32) {
            float e = __expf(S_s[w * 512 + k] - mx);
            S_s[w * 512 + k] = e;
            sm += e;
        }
#pragma unroll
        for (int o = 16; o >= 1; o >>= 1) sm += __shfl_xor_sync(0xffffffffu, sm, o);
        if (l == 0) inv_s[w] = 1.0f / sm;
    }
    __syncthreads();

    // 5. x = S V, write concat-head layout
    {
        const int q = t >> 5, d = t & 31;
        const float* vp = Vt + kb + d;
        const float* sp = S_s + q * 512;
        float a0 = 0, a1 = 0, a2 = 0, a3 = 0;
#pragma unroll 4
        for (int k = 0; k < NK; k += 4) {
            a0 += sp[k + 0] * vp[(k + 0) * 32];
            a1 += sp[k + 1] * vp[(k + 1) * 32];
            a2 += sp[k + 2] * vp[(k + 2) * 32];
            a3 += sp[k + 3] * vp[(k + 3) * 32];
        }
        g_gl[(p * 8 + q) * 256 + a * 32 + d] = (a0 + a1 + a2 + a3) * inv_s[q];
    }
}

// =================================================================
// Kernel 3: qm = g_gl @ nn_O  (512x256 @ 256x256), 32x32 tiles
// =================================================================
__global__ __launch_bounds__(256)
void qm_kernel(const float* __restrict__ nn_O)
{
    __shared__ float A_s[32][33];
    __shared__ float B_s[32][33];
    const int t = threadIdx.x, tx = t & 31, ty = t >> 5;
    const int b0 = blockIdx.x * 32, j0 = blockIdx.y * 32;
    float acc[4] = {0, 0, 0, 0};
    for (int k0 = 0; k0 < 256; k0 += 32) {
        for (int i = t; i < 1024; i += 256) {
            int r = i >> 5, c = i & 31;
            A_s[r][c] = g_gl[(b0 + r) * 256 + k0 + c];
            B_s[r][c] = nn_O[(k0 + r) * 256 + j0 + c];
        }
        __syncthreads();
#pragma unroll
        for (int kk = 0; kk < 32; kk++) {
            float bv = B_s[kk][tx];
            acc[0] += A_s[ty][kk] * bv;
            acc[1] += A_s[ty + 8][kk] * bv;
            acc[2] += A_s[ty + 16][kk] * bv;
            acc[3] += A_s[ty + 24][kk] * bv;
        }
        __syncthreads();
    }
#pragma unroll
    for (int ri = 0; ri < 4; ri++)
        g_qm[(b0 + ty + 8 * ri) * 256 + j0 + tx] = acc[ri];
}

// =================================================================
// Kernel 4: logits.  block = (p, 100-k chunk); phase A computes
// base = X + vf in smem, phase B warp-per-q tanh-dot-reduce.
// =================================================================
__global__ __launch_bounds__(256)
void logits_kernel(const float* __restrict__ X, const float* __restrict__ varfeat,
                   const float* __restrict__ nn_A, const float* __restrict__ nn_B,
                   const float* __restrict__ nn_W)
{
    __shared__ __align__(16) float base_s[8][256];
    __shared__ float qm_s[8 * 256];
    __shared__ float vf_s[8][100];

    const int t  = threadIdx.x;
    const int p  = blockIdx.x;
    const int k0 = blockIdx.y * 100;

    // prologue
    for (int i = t; i < 2048; i += 256) qm_s[i] = g_qm[p * 8 * 256 + i];
    float a_v[8];
#pragma unroll
    for (int v = 0; v < 8; v++) a_v[v] = nn_A[v * 256 + t];
    const float bB = nn_B[t];
    for (int i = t; i < 800; i += 256) {
        int v = i / 100, kk = i - v * 100;
        vf_s[v][kk] = varfeat[(p * 8 + v) * NK + k0 + kk];
    }
    __syncthreads();

    const int w = t >> 5, l = t & 31;
    float qr[8], wr[8];
#pragma unroll
    for (int i = 0; i < 8; i++) {
        qr[i] = qm_s[w * 256 + l * 8 + i];
        wr[i] = nn_W[l * 8 + i];
    }

    for (int kt = 0; kt < 100; kt += 8) {
        const int nk = min(8, 100 - kt);
        // phase A: base = X + vf  (thread t owns h=t)
#pragma unroll
        for (int kk = 0; kk < 8; kk++) {
            if (kk < nk) {
                int kg = k0 + kt + kk;
                float vf = bB;
#pragma unroll
                for (int v = 0; v < 8; v++) vf += vf_s[v][kt + kk] * a_v[v];
                base_s[kk][t] = X[(p * NK + kg) * 256 + t] + vf;
            }
        }
        __syncthreads();
        // phase B: warp w handles q=w; lane covers 8 h values
        for (int kk = 0; kk < nk; kk++) {
            const float4* bp = (const float4*)&base_s[kk][0];
            float4 x0 = bp[l * 2], x1 = bp[l * 2 + 1];
            float s = tanh_acc(x0.x + qr[0]) * wr[0]
                    + tanh_acc(x0.y + qr[1]) * wr[1]
                    + tanh_acc(x0.z + qr[2]) * wr[2]
                    + tanh_acc(x0.w + qr[3]) * wr[3]
                    + tanh_acc(x1.x + qr[4]) * wr[4]
                    + tanh_acc(x1.y + qr[5]) * wr[5]
                    + tanh_acc(x1.z + qr[6]) * wr[6]
                    + tanh_acc(x1.w + qr[7]) * wr[7];
#pragma unroll
            for (int o = 16; o >= 1; o >>= 1) s += __shfl_xor_sync(0xffffffffu, s, o);
            if (l == 0) {
                int kg = k0 + kt + kk;
                int idx = (p * 8 + w) * NK + kg;
                g_logit[idx] = g_mask[idx] ? -1e30f : s;
            }
        }
        __syncthreads();
    }
}

// =================================================================
// Kernel 5: choose.  chosen_p = -log(sum exp(l - max)) per row.
// =================================================================
__global__ __launch_bounds__(128)
void choose_kernel(float* __restrict__ out_p)
{
    __shared__ float red[128];
    const int r = blockIdx.x, t = threadIdx.x;
    const float* row = g_logit + r * NK;

    float mx = -1e30f;
    for (int k = t; k < NK; k += 128) {
        float raw = row[k];
        if (raw > -1e29f) mx = fmaxf(mx, tanhf(raw) * 10.0f);
    }
    red[t] = mx; __syncthreads();
    for (int s = 64; s > 0; s >>= 1) {
        if (t < s) red[t] = fmaxf(red[t], red[t + s]);
        __syncthreads();
    }
    mx = red[0]; __syncthreads();

    float sm = 0.0f;
    for (int k = t; k < NK; k += 128) {
        float raw = row[k];
        if (raw > -1e29f) sm += __expf(tanhf(raw) * 10.0f - mx);
    }
    red[t] = sm; __syncthreads();
    for (int s = 64; s > 0; s >>= 1) {
        if (t < s) red[t] += red[t + s];
        __syncthreads();
    }
    if (t == 0) out_p[r] = -logf(red[0]);
}

// =================================================================
extern "C" void kernel_launch(void* const* d_in, const int* in_sizes, int n_in,
                              void* d_out, int out_size)
{
    const float* X       = (const float*)d_in[0];
    const float* Kt      = (const float*)d_in[1];
    const float* Vt      = (const float*)d_in[2];
    const float* query   = (const float*)d_in[3];
    const float* state1  = (const float*)d_in[4];
    const float* state2  = (const float*)d_in[5];
    const float* varfeat = (const float*)d_in[6];
    const void*  mask    = d_in[7];
    const float* nn_Q    = (const float*)d_in[8];
    const float* nn_O    = (const float*)d_in[9];
    const float* nn_A    = (const float*)d_in[10];
    const float* nn_B    = (const float*)d_in[11];
    const float* nn_W    = (const float*)d_in[12];
    const float* W_ih    = (const float*)d_in[13];
    const float* W_hh    = (const float*)d_in[14];
    const float* b_ih    = (const float*)d_in[15];
    const float* b_hh    = (const float*)d_in[16];

    float* out = (float*)d_out;
    float* out_h = out;                       // [512,256]
    float* out_c = out + 512 * 256;           // [512,256]
    float* out_p = out + 2 * 512 * 256;       // [512]

    detect_mask_kernel<<<1, 1024>>>((const unsigned int*)mask);
    normalize_mask_kernel<<<(BATCH * NK + 255) / 256, 256>>>(mask);
    lstm_kernel<<<dim3(16, 8), 256>>>(query, state1, state2, W_ih, W_hh,
                                      b_ih, b_hh, out_h, out_c);
    glimpse_kernel<<<512, 256>>>(out_h, Kt, Vt, nn_Q);
    qm_kernel<<<dim3(16, 8), 256>>>(nn_O);
    logits_kernel<<<dim3(64, 5), 256>>>(X, varfeat, nn_A, nn_B, nn_W);
    choose_kernel<<<512, 128>>>(out_p);
}

// round 3
// speedup vs baseline: 1.3454x; 1.3454x over previous
#include <cuda_runtime.h>
#include <math.h>

#define NPROB  64
#define NRR    8
#define NK     500
#define HDIM   256
#define NHEADS 8
#define HD     32
#define BATCH  512   // NPROB*NRR
#define KHALF  250   // NK / 2 k-split for glimpse

// ---------------- scratch (no allocations allowed) ----------------
__device__ float g_gl[BATCH * HDIM];       // glimpse (concat heads), [b][H]
__device__ float g_qm[BATCH * HDIM];       // glimpse @ nn_O
__device__ float g_logit[BATCH * NK];      // masked logits (-1e30 sentinel)
__device__ int   g_mask_mode;              // 0=u8,1=i32,2=f32,3=bf16
__device__ unsigned char g_mask[BATCH * NK];
__device__ float g_att_part[2 * NHEADS * NPROB * NRR * HD];  // [half][a][p][q][d]
__device__ float2 g_att_ms[2 * NHEADS * NPROB * NRR];        // (max, sumexp)
__device__ float g_lstm_part[2 * BATCH * 4 * HDIM];          // [half][b][g*256+j]

// exact tanh: 1 - 2/(exp(2x)+1); 2 MUFU, saturates correctly
__device__ __forceinline__ float tanh_acc(float x) {
    float e = __expf(2.0f * x);
    return 1.0f - __fdividef(2.0f, e + 1.0f);
}
__device__ __forceinline__ float sigmoidf_(float x) {
    return 1.0f / (1.0f + __expf(-x));
}

// =================================================================
// Kernel 0a: detect mask dtype from raw bits. First 8000 words are
// in-bounds for every candidate dtype (u8 buffer = 64000 words).
// =================================================================
__global__ void detect_mask_kernel(const unsigned int* __restrict__ mraw)
{
    __shared__ int s_i32, s_f32, s_bf16;
    const int t = threadIdx.x;
    if (t == 0) { s_i32 = 1; s_f32 = 1; s_bf16 = 1; }
    __syncthreads();
    int ok_i32 = 1, ok_f32 = 1, ok_bf16 = 1;
    for (int i = t; i < 8000; i += blockDim.x) {
        unsigned int w = mraw[i];
        ok_i32  &= (w <= 1u);
        ok_f32  &= (w == 0u || w == 0x3F800000u);
        unsigned int lo = w & 0xFFFFu, hi = w >> 16;
        ok_bf16 &= (lo == 0u || lo == 0x3F80u) && (hi == 0u || hi == 0x3F80u);
    }
    if (!ok_i32)  atomicAnd(&s_i32, 0);
    if (!ok_f32)  atomicAnd(&s_f32, 0);
    if (!ok_bf16) atomicAnd(&s_bf16, 0);
    __syncthreads();
    if (t == 0) {
        int mode = 0;
        if (s_i32) mode = 1;
        else if (s_f32) mode = 2;
        else if (s_bf16) mode = 3;
        g_mask_mode = mode;
    }
}

// =================================================================
// Kernel 0b: normalize mask to bytes in g_mask
// =================================================================
__global__ void normalize_mask_kernel(const void* __restrict__ mraw)
{
    const int idx = blockIdx.x * blockDim.x + threadIdx.x;
    if (idx >= BATCH * NK) return;
    const int mode = g_mask_mode;
    unsigned char v;
    if (mode == 1)      v = (((const int*)mraw)[idx] != 0);
    else if (mode == 2) v = (((const unsigned int*)mraw)[idx] != 0u);
    else if (mode == 3) v = (((const unsigned short*)mraw)[idx] != 0u);
    else                v = (((const unsigned char*)mraw)[idx] != 0u);
    g_mask[idx] = v;
}

// =================================================================
// Kernel 1a: LSTM GEMM halves.  half 0: query @ W_ih^T;
//            half 1: state1 @ W_hh^T.  Partial sums to scratch.
// =================================================================
__global__ __launch_bounds__(256)
void lstm_part_kernel(const float* __restrict__ query, const float* __restrict__ state1,
                      const float* __restrict__ W_ih, const float* __restrict__ W_hh)
{
    __shared__ float A_s[32][33];
    __shared__ float W_s[4][32][33];
    const int t  = threadIdx.x;
    const int tx = t & 31, ty = t >> 5;
    const int b0 = blockIdx.x * 32, j0 = blockIdx.y * 32;
    const int half = blockIdx.z;
    const int lrow = t >> 3, lk = (t & 7) * 4;
    const float* Abase = half ? state1 : query;
    const float* Wbase = half ? W_hh : W_ih;

    float acc[4][4];
#pragma unroll
    for (int i = 0; i < 4; i++)
#pragma unroll
        for (int j = 0; j < 4; j++) acc[i][j] = 0.0f;

    for (int k0 = 0; k0 < 256; k0 += 32) {
        float4 av = *(const float4*)&Abase[(b0 + lrow) * 256 + k0 + lk];
        A_s[lrow][lk + 0] = av.x; A_s[lrow][lk + 1] = av.y;
        A_s[lrow][lk + 2] = av.z; A_s[lrow][lk + 3] = av.w;
#pragma unroll
        for (int gg = 0; gg < 4; gg++) {
            float4 wv = *(const float4*)&Wbase[(gg * 256 + j0 + lrow) * 256 + k0 + lk];
            W_s[gg][lrow][lk + 0] = wv.x; W_s[gg][lrow][lk + 1] = wv.y;
            W_s[gg][lrow][lk + 2] = wv.z; W_s[gg][lrow][lk + 3] = wv.w;
        }
        __syncthreads();
#pragma unroll
        for (int kk = 0; kk < 32; kk++) {
            float a0 = A_s[ty][kk], a1 = A_s[ty + 8][kk];
            float a2 = A_s[ty + 16][kk], a3 = A_s[ty + 24][kk];
            float w0 = W_s[0][tx][kk], w1 = W_s[1][tx][kk];
            float w2 = W_s[2][tx][kk], w3 = W_s[3][tx][kk];
            acc[0][0] += a0 * w0; acc[0][1] += a0 * w1; acc[0][2] += a0 * w2; acc[0][3] += a0 * w3;
            acc[1][0] += a1 * w0; acc[1][1] += a1 * w1; acc[1][2] += a1 * w2; acc[1][3] += a1 * w3;
            acc[2][0] += a2 * w0; acc[2][1] += a2 * w1; acc[2][2] += a2 * w2; acc[2][3] += a2 * w3;
            acc[3][0] += a3 * w0; acc[3][1] += a3 * w1; acc[3][2] += a3 * w2; acc[3][3] += a3 * w3;
        }
        __syncthreads();
    }
#pragma unroll
    for (int ri = 0; ri < 4; ri++) {
        const int b = b0 + ty + 8 * ri;
#pragma unroll
        for (int gg = 0; gg < 4; gg++)
            g_lstm_part[(half * BATCH + b) * 1024 + gg * 256 + j0 + tx] = acc[ri][gg];
    }
}

// =================================================================
// Kernel 1b: LSTM pointwise: combine halves + biases, gate math.
// =================================================================
__global__ __launch_bounds__(256)
void lstm_point_kernel(const float* __restrict__ state2,
                       const float* __restrict__ b_ih, const float* __restrict__ b_hh,
                       float* __restrict__ out_h, float* __restrict__ out_c)
{
    const int idx = blockIdx.x * 256 + threadIdx.x;   // b*256 + j
    const int b = idx >> 8, j = idx & 255;
    const float* p0 = g_lstm_part + b * 1024;
    const float* p1 = g_lstm_part + (BATCH + b) * 1024;
    float gi = p0[j]       + p1[j]       + b_ih[j]       + b_hh[j];
    float gf = p0[256 + j] + p1[256 + j] + b_ih[256 + j] + b_hh[256 + j];
    float gg = p0[512 + j] + p1[512 + j] + b_ih[512 + j] + b_hh[512 + j];
    float go = p0[768 + j] + p1[768 + j] + b_ih[768 + j] + b_hh[768 + j];
    float c = sigmoidf_(gf) * state2[idx] + sigmoidf_(gi) * tanh_acc(gg);
    float h = sigmoidf_(go) * tanh_acc(c);
    out_h[idx] = h;
    out_c[idx] = c;
}

// =================================================================
// Kernel 2a: glimpse attention partials.  block = (half, head a, problem p).
// Computes partial softmax stats + unnormalized SV over 250 keys.
// =================================================================
__global__ __launch_bounds__(256)
void glimpse_part_kernel(const float* __restrict__ h_in, const float* __restrict__ Kt,
                         const float* __restrict__ Vt, const float* __restrict__ nn_Q)
{
    __shared__ float q_s[8 * 256];
    __shared__ __align__(16) float Q_s[8 * 32];
    __shared__ float S_s[8 * 256];
    __shared__ float K_s[64 * 33];

    const int t = threadIdx.x;
    const int half = blockIdx.x >> 9;
    const int a = (blockIdx.x >> 6) & 7;
    const int p = blockIdx.x & 63;
    const int kb = (a * 64 + p) * NK * HD;
    const int kbase = half * KHALF;

    // 1. stage q
    for (int i = t; i < 2048; i += 256) q_s[i] = h_in[p * 8 * 256 + i];
    __syncthreads();

    // 2. Q = q @ nn_Q[a] * 1/sqrt(HD)
    {
        const int q = t >> 5, d = t & 31;
        const float* qn = nn_Q + a * 256 * 32 + d;
        const float* qr = q_s + q * 256;
        float s0 = 0, s1 = 0, s2 = 0, s3 = 0;
#pragma unroll 4
        for (int hh = 0; hh < 256; hh += 4) {
            s0 += qr[hh + 0] * qn[(hh + 0) * 32];
            s1 += qr[hh + 1] * qn[(hh + 1) * 32];
            s2 += qr[hh + 2] * qn[(hh + 2) * 32];
            s3 += qr[hh + 3] * qn[(hh + 3) * 32];
        }
        Q_s[q * 32 + d] = (s0 + s1 + s2 + s3) * 0.17677669529663687f;
    }
    __syncthreads();

    // 3. S = Q K^T (masked), staged K chunks of 64 rows (250 keys)
    const int kloc = t & 63, qp = t >> 6;
    const int q0 = qp * 2, q1 = q0 + 1;
    for (int c0 = 0; c0 < KHALF; c0 += 64) {
        for (int i = t; i < 2048; i += 256) {
            int row = i >> 5, d = i & 31;
            if (c0 + row < KHALF)
                K_s[row * 33 + d] = Kt[kb + (kbase + c0 + row) * 32 + d];
        }
        __syncthreads();
        int kl = c0 + kloc;
        if (kl < KHALF) {
            int kg = kbase + kl;
            float acc0 = 0, acc1 = 0;
            const float4* Qs4 = (const float4*)Q_s;
#pragma unroll
            for (int d4 = 0; d4 < 8; d4++) {
                float4 qa = Qs4[q0 * 8 + d4];
                float4 qb = Qs4[q1 * 8 + d4];
                int kbs = kloc * 33 + d4 * 4;
                float k0v = K_s[kbs], k1v = K_s[kbs + 1];
                float k2v = K_s[kbs + 2], k3v = K_s[kbs + 3];
                acc0 += k0v * qa.x + k1v * qa.y + k2v * qa.z + k3v * qa.w;
                acc1 += k0v * qb.x + k1v * qb.y + k2v * qb.z + k3v * qb.w;
            }
            S_s[q0 * 256 + kl] = g_mask[(p * 8 + q0) * NK + kg] ? -1e30f : acc0;
            S_s[q1 * 256 + kl] = g_mask[(p * 8 + q1) * NK + kg] ? -1e30f : acc1;
        }
        __syncthreads();
    }

    // 4. partial softmax stats per q (warp w -> q = w)
    {
        const int w = t >> 5, l = t & 31;
        float mx = -1e30f;
        for (int k = l; k < KHALF; k += 32) mx = fmaxf(mx, S_s[w * 256 + k]);
#pragma unroll
        for (int o = 16; o >= 1; o >>= 1) mx = fmaxf(mx, __shfl_xor_sync(0xffffffffu, mx, o));
        float sm = 0;
        for (int k = l; k < KHALF; k += 32) {
            float e = __expf(S_s[w * 256 + k] - mx);
            S_s[w * 256 + k] = e;
            sm += e;
        }
#pragma unroll
        for (int o = 16; o >= 1; o >>= 1) sm += __shfl_xor_sync(0xffffffffu, sm, o);
        if (l == 0)
            g_att_ms[((half * 8 + a) * 64 + p) * 8 + w] = make_float2(mx, sm);
    }
    __syncthreads();

    // 5. partial (unnormalized) x = S V
    {
        const int q = t >> 5, d = t & 31;
        const float* vp = Vt + kb + kbase * 32 + d;
        const float* sp = S_s + q * 256;
        float a0 = 0, a1 = 0, a2 = 0, a3 = 0, a4 = 0;
#pragma unroll 10
        for (int k = 0; k < KHALF; k += 5) {
            a0 += sp[k + 0] * vp[(k + 0) * 32];
            a1 += sp[k + 1] * vp[(k + 1) * 32];
            a2 += sp[k + 2] * vp[(k + 2) * 32];
            a3 += sp[k + 3] * vp[(k + 3) * 32];
            a4 += sp[k + 4] * vp[(k + 4) * 32];
        }
        g_att_part[(((half * 8 + a) * 64 + p) * 8 + q) * 32 + d] = a0 + a1 + a2 + a3 + a4;
    }
}

// =================================================================
// Kernel 2b: combine the two k-halves into g_gl.
// block = (p,q) [512], thread = (a,d).
// =================================================================
__global__ __launch_bounds__(256)
void glimpse_combine_kernel()
{
    const int p = blockIdx.x >> 3, q = blockIdx.x & 7;
    const int t = threadIdx.x, a = t >> 5, d = t & 31;
    const int i0 = ((0 * 8 + a) * 64 + p) * 8 + q;
    const int i1 = ((1 * 8 + a) * 64 + p) * 8 + q;
    float2 ms0 = g_att_ms[i0];
    float2 ms1 = g_att_ms[i1];
    float m = fmaxf(ms0.x, ms1.x);
    float w0 = __expf(ms0.x - m), w1 = __expf(ms1.x - m);
    float den = ms0.y * w0 + ms1.y * w1;
    float P0 = g_att_part[i0 * 32 + d];
    float P1 = g_att_part[i1 * 32 + d];
    g_gl[(p * 8 + q) * 256 + a * 32 + d] = (P0 * w0 + P1 * w1) / den;
}

// =================================================================
// Kernel 3: qm = g_gl @ nn_O  (512x256 @ 256x256)
// =================================================================
__global__ __launch_bounds__(256)
void qm_kernel(const float* __restrict__ nn_O)
{
    __shared__ float A_s[32][33];
    __shared__ float B_s[32][33];
    const int t = threadIdx.x, tx = t & 31, ty = t >> 5;
    const int b0 = blockIdx.x * 32, j0 = blockIdx.y * 32;
    float acc[4] = {0, 0, 0, 0};
    for (int k0 = 0; k0 < 256; k0 += 32) {
        for (int i = t; i < 1024; i += 256) {
            int r = i >> 5, c = i & 31;
            A_s[r][c] = g_gl[(b0 + r) * 256 + k0 + c];
            B_s[r][c] = nn_O[(k0 + r) * 256 + j0 + c];
        }
        __syncthreads();
#pragma unroll
        for (int kk = 0; kk < 32; kk++) {
            float bv = B_s[kk][tx];
            acc[0] += A_s[ty][kk] * bv;
            acc[1] += A_s[ty + 8][kk] * bv;
            acc[2] += A_s[ty + 16][kk] * bv;
            acc[3] += A_s[ty + 24][kk] * bv;
        }
        __syncthreads();
    }
#pragma unroll
    for (int ri = 0; ri < 4; ri++)
        g_qm[(b0 + ty + 8 * ri) * 256 + j0 + tx] = acc[ri];
}

// =================================================================
// Kernel 4: logits.  block = (p, 25-k chunk) -> grid (64,20).
// =================================================================
__global__ __launch_bounds__(256)
void logits_kernel(const float* __restrict__ X, const float* __restrict__ varfeat,
                   const float* __restrict__ nn_A, const float* __restrict__ nn_B,
                   const float* __restrict__ nn_W)
{
    __shared__ __align__(16) float base_s[5][256];
    __shared__ float qm_s[8 * 256];
    __shared__ float vf_s[8][25];

    const int t  = threadIdx.x;
    const int p  = blockIdx.x;
    const int k0 = blockIdx.y * 25;

    for (int i = t; i < 2048; i += 256) qm_s[i] = g_qm[p * 8 * 256 + i];
    float a_v[8];
#pragma unroll
    for (int v = 0; v < 8; v++) a_v[v] = nn_A[v * 256 + t];
    const float bB = nn_B[t];
    for (int i = t; i < 200; i += 256) {
        int v = i / 25, kk = i - v * 25;
        vf_s[v][kk] = varfeat[(p * 8 + v) * NK + k0 + kk];
    }
    __syncthreads();

    const int w = t >> 5, l = t & 31;
    float qr[8], wr[8];
#pragma unroll
    for (int i = 0; i < 8; i++) {
        qr[i] = qm_s[w * 256 + l * 8 + i];
        wr[i] = nn_W[l * 8 + i];
    }

    for (int kt = 0; kt < 25; kt += 5) {
        // phase A: base = X + vf  (thread t owns h=t)
#pragma unroll
        for (int kk = 0; kk < 5; kk++) {
            int kg = k0 + kt + kk;
            float vf = bB;
#pragma unroll
            for (int v = 0; v < 8; v++) vf += vf_s[v][kt + kk] * a_v[v];
            base_s[kk][t] = X[(p * NK + kg) * 256 + t] + vf;
        }
        __syncthreads();
        // phase B: warp w handles q=w; lane covers 8 h values
#pragma unroll
        for (int kk = 0; kk < 5; kk++) {
            const float4* bp = (const float4*)&base_s[kk][0];
            float4 x0 = bp[l * 2], x1 = bp[l * 2 + 1];
            float s = tanh_acc(x0.x + qr[0]) * wr[0]
                    + tanh_acc(x0.y + qr[1]) * wr[1]
                    + tanh_acc(x0.z + qr[2]) * wr[2]
                    + tanh_acc(x0.w + qr[3]) * wr[3]
                    + tanh_acc(x1.x + qr[4]) * wr[4]
                    + tanh_acc(x1.y + qr[5]) * wr[5]
                    + tanh_acc(x1.z + qr[6]) * wr[6]
                    + tanh_acc(x1.w + qr[7]) * wr[7];
#pragma unroll
            for (int o = 16; o >= 1; o >>= 1) s += __shfl_xor_sync(0xffffffffu, s, o);
            if (l == 0) {
                int idx = (p * 8 + w) * NK + k0 + kt + kk;
                g_logit[idx] = g_mask[idx] ? -1e30f : s;
            }
        }
        __syncthreads();
    }
}

// =================================================================
// Kernel 5: choose.  chosen_p = -log(sum exp(l - max)) per row.
// =================================================================
__global__ __launch_bounds__(128)
void choose_kernel(float* __restrict__ out_p)
{
    __shared__ float red[128];
    const int r = blockIdx.x, t = threadIdx.x;
    const float* row = g_logit + r * NK;

    float mx = -1e30f;
    for (int k = t; k < NK; k += 128) {
        float raw = row[k];
        if (raw > -1e29f) mx = fmaxf(mx, tanh_acc(raw) * 10.0f);
    }
    red[t] = mx; __syncthreads();
    for (int s = 64; s > 0; s >>= 1) {
        if (t < s) red[t] = fmaxf(red[t], red[t + s]);
        __syncthreads();
    }
    mx = red[0]; __syncthreads();

    float sm = 0.0f;
    for (int k = t; k < NK; k += 128) {
        float raw = row[k];
        if (raw > -1e29f) sm += __expf(tanh_acc(raw) * 10.0f - mx);
    }
    red[t] = sm; __syncthreads();
    for (int s = 64; s > 0; s >>= 1) {
        if (t < s) red[t] += red[t + s];
        __syncthreads();
    }
    if (t == 0) out_p[r] = -logf(red[0]);
}

// =================================================================
extern "C" void kernel_launch(void* const* d_in, const int* in_sizes, int n_in,
                              void* d_out, int out_size)
{
    const float* X       = (const float*)d_in[0];
    const float* Kt      = (const float*)d_in[1];
    const float* Vt      = (const float*)d_in[2];
    const float* query   = (const float*)d_in[3];
    const float* state1  = (const float*)d_in[4];
    const float* state2  = (const float*)d_in[5];
    const float* varfeat = (const float*)d_in[6];
    const void*  mask    = d_in[7];
    const float* nn_Q    = (const float*)d_in[8];
    const float* nn_O    = (const float*)d_in[9];
    const float* nn_A    = (const float*)d_in[10];
    const float* nn_B    = (const float*)d_in[11];
    const float* nn_W    = (const float*)d_in[12];
    const float* W_ih    = (const float*)d_in[13];
    const float* W_hh    = (const float*)d_in[14];
    const float* b_ih    = (const float*)d_in[15];
    const float* b_hh    = (const float*)d_in[16];

    float* out = (float*)d_out;
    float* out_h = out;                       // [512,256]
    float* out_c = out + 512 * 256;           // [512,256]
    float* out_p = out + 2 * 512 * 256;       // [512]

    detect_mask_kernel<<<1, 1024>>>((const unsigned int*)mask);
    normalize_mask_kernel<<<(BATCH * NK + 255) / 256, 256>>>(mask);
    lstm_part_kernel<<<dim3(16, 8, 2), 256>>>(query, state1, W_ih, W_hh);
    lstm_point_kernel<<<512, 256>>>(state2, b_ih, b_hh, out_h, out_c);
    glimpse_part_kernel<<<1024, 256>>>(out_h, Kt, Vt, nn_Q);
    glimpse_combine_kernel<<<512, 256>>>();
    qm_kernel<<<dim3(16, 8), 256>>>(nn_O);
    logits_kernel<<<dim3(64, 20), 256>>>(X, varfeat, nn_A, nn_B, nn_W);
    choose_kernel<<<512, 128>>>(out_p);
}

// round 4
// speedup vs baseline: 1.3622x; 1.0125x over previous
#include <cuda_runtime.h>
#include <math.h>

#define NPROB  64
#define NRR    8
#define NK     500
#define HDIM   256
#define NHEADS 8
#define HD     32
#define BATCH  512   // NPROB*NRR
#define KHALF  250   // NK / 2 k-split for glimpse

// ---------------- scratch (no allocations allowed) ----------------
__device__ float g_gl[BATCH * HDIM];       // glimpse (concat heads), [b][H]
__device__ float g_qm[BATCH * HDIM];       // glimpse @ nn_O
__device__ float g_logit[BATCH * NK];      // masked logits (-1e30 sentinel)
__device__ int   g_mask_mode;              // 0=u8,1=i32,2=f32,3=bf16
__device__ unsigned char g_mask[BATCH * NK];
__device__ float g_att_part[2 * NHEADS * NPROB * NRR * HD];  // [half][a][p][q][d]
__device__ float2 g_att_ms[2 * NHEADS * NPROB * NRR];        // (max, sumexp)
__device__ float g_lstm_part[2 * BATCH * 4 * HDIM];          // [half][b][g*256+j]

// single-instruction MUFU.TANH (abs err ~2^-10.6) -- hot path only
__device__ __forceinline__ float fast_tanh(float x) {
    float y;
    asm("tanh.approx.f32 %0, %1;" : "=f"(y) : "f"(x));
    return y;
}
// exact tanh: 1 - 2/(exp(2x)+1)
__device__ __forceinline__ float tanh_acc(float x) {
    float e = __expf(2.0f * x);
    return 1.0f - __fdividef(2.0f, e + 1.0f);
}
__device__ __forceinline__ float sigmoidf_(float x) {
    return 1.0f / (1.0f + __expf(-x));
}

// =================================================================
// Kernel 0a: detect mask dtype from raw bits. First 8000 words are
// in-bounds for every candidate dtype (u8 buffer = 64000 words).
// =================================================================
__global__ void detect_mask_kernel(const unsigned int* __restrict__ mraw)
{
    __shared__ int s_i32, s_f32, s_bf16;
    const int t = threadIdx.x;
    if (t == 0) { s_i32 = 1; s_f32 = 1; s_bf16 = 1; }
    __syncthreads();
    int ok_i32 = 1, ok_f32 = 1, ok_bf16 = 1;
    for (int i = t; i < 8000; i += blockDim.x) {
        unsigned int w = mraw[i];
        ok_i32  &= (w <= 1u);
        ok_f32  &= (w == 0u || w == 0x3F800000u);
        unsigned int lo = w & 0xFFFFu, hi = w >> 16;
        ok_bf16 &= (lo == 0u || lo == 0x3F80u) && (hi == 0u || hi == 0x3F80u);
    }
    if (!ok_i32)  atomicAnd(&s_i32, 0);
    if (!ok_f32)  atomicAnd(&s_f32, 0);
    if (!ok_bf16) atomicAnd(&s_bf16, 0);
    __syncthreads();
    if (t == 0) {
        int mode = 0;
        if (s_i32) mode = 1;
        else if (s_f32) mode = 2;
        else if (s_bf16) mode = 3;
        g_mask_mode = mode;
    }
}

// =================================================================
// Kernel 0b: normalize mask to bytes in g_mask
// =================================================================
__global__ void normalize_mask_kernel(const void* __restrict__ mraw)
{
    const int idx = blockIdx.x * blockDim.x + threadIdx.x;
    if (idx >= BATCH * NK) return;
    const int mode = g_mask_mode;
    unsigned char v;
    if (mode == 1)      v = (((const int*)mraw)[idx] != 0);
    else if (mode == 2) v = (((const unsigned int*)mraw)[idx] != 0u);
    else if (mode == 3) v = (((const unsigned short*)mraw)[idx] != 0u);
    else                v = (((const unsigned char*)mraw)[idx] != 0u);
    g_mask[idx] = v;
}

// =================================================================
// Kernel 1a: LSTM GEMM halves.  half 0: query @ W_ih^T;
//            half 1: state1 @ W_hh^T.  Partial sums to scratch.
// =================================================================
__global__ __launch_bounds__(256)
void lstm_part_kernel(const float* __restrict__ query, const float* __restrict__ state1,
                      const float* __restrict__ W_ih, const float* __restrict__ W_hh)
{
    __shared__ float A_s[32][33];
    __shared__ float W_s[4][32][33];
    const int t  = threadIdx.x;
    const int tx = t & 31, ty = t >> 5;
    const int b0 = blockIdx.x * 32, j0 = blockIdx.y * 32;
    const int half = blockIdx.z;
    const int lrow = t >> 3, lk = (t & 7) * 4;
    const float* Abase = half ? state1 : query;
    const float* Wbase = half ? W_hh : W_ih;

    float acc[4][4];
#pragma unroll
    for (int i = 0; i < 4; i++)
#pragma unroll
        for (int j = 0; j < 4; j++) acc[i][j] = 0.0f;

    for (int k0 = 0; k0 < 256; k0 += 32) {
        float4 av = *(const float4*)&Abase[(b0 + lrow) * 256 + k0 + lk];
        A_s[lrow][lk + 0] = av.x; A_s[lrow][lk + 1] = av.y;
        A_s[lrow][lk + 2] = av.z; A_s[lrow][lk + 3] = av.w;
#pragma unroll
        for (int gg = 0; gg < 4; gg++) {
            float4 wv = *(const float4*)&Wbase[(gg * 256 + j0 + lrow) * 256 + k0 + lk];
            W_s[gg][lrow][lk + 0] = wv.x; W_s[gg][lrow][lk + 1] = wv.y;
            W_s[gg][lrow][lk + 2] = wv.z; W_s[gg][lrow][lk + 3] = wv.w;
        }
        __syncthreads();
#pragma unroll
        for (int kk = 0; kk < 32; kk++) {
            float a0 = A_s[ty][kk], a1 = A_s[ty + 8][kk];
            float a2 = A_s[ty + 16][kk], a3 = A_s[ty + 24][kk];
            float w0 = W_s[0][tx][kk], w1 = W_s[1][tx][kk];
            float w2 = W_s[2][tx][kk], w3 = W_s[3][tx][kk];
            acc[0][0] += a0 * w0; acc[0][1] += a0 * w1; acc[0][2] += a0 * w2; acc[0][3] += a0 * w3;
            acc[1][0] += a1 * w0; acc[1][1] += a1 * w1; acc[1][2] += a1 * w2; acc[1][3] += a1 * w3;
            acc[2][0] += a2 * w0; acc[2][1] += a2 * w1; acc[2][2] += a2 * w2; acc[2][3] += a2 * w3;
            acc[3][0] += a3 * w0; acc[3][1] += a3 * w1; acc[3][2] += a3 * w2; acc[3][3] += a3 * w3;
        }
        __syncthreads();
    }
#pragma unroll
    for (int ri = 0; ri < 4; ri++) {
        const int b = b0 + ty + 8 * ri;
#pragma unroll
        for (int gg = 0; gg < 4; gg++)
            g_lstm_part[(half * BATCH + b) * 1024 + gg * 256 + j0 + tx] = acc[ri][gg];
    }
}

// =================================================================
// Kernel 1b: LSTM pointwise (float4): combine halves + biases, gates.
// thread handles 4 consecutive j.  grid 128 x 256.
// =================================================================
__global__ __launch_bounds__(256)
void lstm_point_kernel(const float* __restrict__ state2,
                       const float* __restrict__ b_ih, const float* __restrict__ b_hh,
                       float* __restrict__ out_h, float* __restrict__ out_c)
{
    const int v = blockIdx.x * 256 + threadIdx.x;     // vec4 index over b*64 + j4
    const int b = v >> 6, j4 = (v & 63) * 4;
    const float4* p0 = (const float4*)(g_lstm_part + b * 1024);
    const float4* p1 = (const float4*)(g_lstm_part + (BATCH + b) * 1024);
    const float4* bi = (const float4*)b_ih;
    const float4* bh = (const float4*)b_hh;
    const int jv = j4 >> 2;
    float4 gi4, gf4, gg4, go4;
    {
        float4 x0 = p0[jv],        x1 = p1[jv],        y0 = bi[jv],        y1 = bh[jv];
        gi4 = make_float4(x0.x + x1.x + y0.x + y1.x, x0.y + x1.y + y0.y + y1.y,
                          x0.z + x1.z + y0.z + y1.z, x0.w + x1.w + y0.w + y1.w);
    }
    {
        float4 x0 = p0[64 + jv],   x1 = p1[64 + jv],   y0 = bi[64 + jv],   y1 = bh[64 + jv];
        gf4 = make_float4(x0.x + x1.x + y0.x + y1.x, x0.y + x1.y + y0.y + y1.y,
                          x0.z + x1.z + y0.z + y1.z, x0.w + x1.w + y0.w + y1.w);
    }
    {
        float4 x0 = p0[128 + jv],  x1 = p1[128 + jv],  y0 = bi[128 + jv],  y1 = bh[128 + jv];
        gg4 = make_float4(x0.x + x1.x + y0.x + y1.x, x0.y + x1.y + y0.y + y1.y,
                          x0.z + x1.z + y0.z + y1.z, x0.w + x1.w + y0.w + y1.w);
    }
    {
        float4 x0 = p0[192 + jv],  x1 = p1[192 + jv],  y0 = bi[192 + jv],  y1 = bh[192 + jv];
        go4 = make_float4(x0.x + x1.x + y0.x + y1.x, x0.y + x1.y + y0.y + y1.y,
                          x0.z + x1.z + y0.z + y1.z, x0.w + x1.w + y0.w + y1.w);
    }
    float4 s2 = ((const float4*)state2)[b * 64 + jv];
    float4 c4, h4;
    c4.x = sigmoidf_(gf4.x) * s2.x + sigmoidf_(gi4.x) * tanh_acc(gg4.x);
    c4.y = sigmoidf_(gf4.y) * s2.y + sigmoidf_(gi4.y) * tanh_acc(gg4.y);
    c4.z = sigmoidf_(gf4.z) * s2.z + sigmoidf_(gi4.z) * tanh_acc(gg4.z);
    c4.w = sigmoidf_(gf4.w) * s2.w + sigmoidf_(gi4.w) * tanh_acc(gg4.w);
    h4.x = sigmoidf_(go4.x) * tanh_acc(c4.x);
    h4.y = sigmoidf_(go4.y) * tanh_acc(c4.y);
    h4.z = sigmoidf_(go4.z) * tanh_acc(c4.z);
    h4.w = sigmoidf_(go4.w) * tanh_acc(c4.w);
    ((float4*)out_h)[b * 64 + jv] = h4;
    ((float4*)out_c)[b * 64 + jv] = c4;
}

// =================================================================
// Kernel 2a: glimpse attention partials.  block = (half, head a, problem p).
// K and V both staged through smem (V was 8x redundant from global).
// =================================================================
__global__ __launch_bounds__(256)
void glimpse_part_kernel(const float* __restrict__ h_in, const float* __restrict__ Kt,
                         const float* __restrict__ Vt, const float* __restrict__ nn_Q)
{
    __shared__ float q_s[8 * 256];
    __shared__ __align__(16) float Q_s[8 * 32];
    __shared__ float S_s[8 * 256];
    __shared__ float K_s[64 * 33];

    const int t = threadIdx.x;
    const int half = blockIdx.x >> 9;
    const int a = (blockIdx.x >> 6) & 7;
    const int p = blockIdx.x & 63;
    const int kb = (a * 64 + p) * NK * HD;
    const int kbase = half * KHALF;

    // 1. stage q
    for (int i = t; i < 2048; i += 256) q_s[i] = h_in[p * 8 * 256 + i];
    __syncthreads();

    // 2. Q = q @ nn_Q[a] * 1/sqrt(HD)
    {
        const int q = t >> 5, d = t & 31;
        const float* qn = nn_Q + a * 256 * 32 + d;
        const float* qr = q_s + q * 256;
        float s0 = 0, s1 = 0, s2 = 0, s3 = 0;
#pragma unroll 4
        for (int hh = 0; hh < 256; hh += 4) {
            s0 += qr[hh + 0] * qn[(hh + 0) * 32];
            s1 += qr[hh + 1] * qn[(hh + 1) * 32];
            s2 += qr[hh + 2] * qn[(hh + 2) * 32];
            s3 += qr[hh + 3] * qn[(hh + 3) * 32];
        }
        Q_s[q * 32 + d] = (s0 + s1 + s2 + s3) * 0.17677669529663687f;
    }
    __syncthreads();

    // 3. S = Q K^T (masked), staged K chunks of 64 rows (250 keys)
    const int kloc = t & 63, qp = t >> 6;
    const int q0 = qp * 2, q1 = q0 + 1;
    for (int c0 = 0; c0 < KHALF; c0 += 64) {
        for (int i = t; i < 2048; i += 256) {
            int row = i >> 5, d = i & 31;
            if (c0 + row < KHALF)
                K_s[row * 33 + d] = Kt[kb + (kbase + c0 + row) * 32 + d];
        }
        __syncthreads();
        int kl = c0 + kloc;
        if (kl < KHALF) {
            int kg = kbase + kl;
            float acc0 = 0, acc1 = 0;
            const float4* Qs4 = (const float4*)Q_s;
#pragma unroll
            for (int d4 = 0; d4 < 8; d4++) {
                float4 qa = Qs4[q0 * 8 + d4];
                float4 qb = Qs4[q1 * 8 + d4];
                int kbs = kloc * 33 + d4 * 4;
                float k0v = K_s[kbs], k1v = K_s[kbs + 1];
                float k2v = K_s[kbs + 2], k3v = K_s[kbs + 3];
                acc0 += k0v * qa.x + k1v * qa.y + k2v * qa.z + k3v * qa.w;
                acc1 += k0v * qb.x + k1v * qb.y + k2v * qb.z + k3v * qb.w;
            }
            S_s[q0 * 256 + kl] = g_mask[(p * 8 + q0) * NK + kg] ? -1e30f : acc0;
            S_s[q1 * 256 + kl] = g_mask[(p * 8 + q1) * NK + kg] ? -1e30f : acc1;
        }
        __syncthreads();
    }

    // 4. partial softmax stats per q (warp w -> q = w); zero-pad [250,256)
    {
        const int w = t >> 5, l = t & 31;
        float mx = -1e30f;
        for (int k = l; k < KHALF; k += 32) mx = fmaxf(mx, S_s[w * 256 + k]);
#pragma unroll
        for (int o = 16; o >= 1; o >>= 1) mx = fmaxf(mx, __shfl_xor_sync(0xffffffffu, mx, o));
        float sm = 0;
        for (int k = l; k < KHALF; k += 32) {
            float e = __expf(S_s[w * 256 + k] - mx);
            S_s[w * 256 + k] = e;
            sm += e;
        }
#pragma unroll
        for (int o = 16; o >= 1; o >>= 1) sm += __shfl_xor_sync(0xffffffffu, sm, o);
        if (l == 0)
            g_att_ms[((half * 8 + a) * 64 + p) * 8 + w] = make_float2(mx, sm);
        for (int k = KHALF + l; k < 256; k += 32) S_s[w * 256 + k] = 0.0f;
    }

    // 5. partial (unnormalized) x = S V, V staged through smem chunks
    {
        const int q = t >> 5, d = t & 31;
        float a0 = 0, a1 = 0, a2 = 0, a3 = 0;
        for (int c0 = 0; c0 < 256; c0 += 64) {
            __syncthreads();
            for (int i = t; i < 2048; i += 256) {
                int row = i >> 5, dd = i & 31;
                K_s[row * 33 + dd] = (c0 + row < KHALF)
                    ? Vt[kb + (kbase + c0 + row) * 32 + dd] : 0.0f;
            }
            __syncthreads();
            const float* sp = S_s + q * 256 + c0;
#pragma unroll
            for (int kk = 0; kk < 64; kk += 4) {
                a0 += sp[kk + 0] * K_s[(kk + 0) * 33 + d];
                a1 += sp[kk + 1] * K_s[(kk + 1) * 33 + d];
                a2 += sp[kk + 2] * K_s[(kk + 2) * 33 + d];
                a3 += sp[kk + 3] * K_s[(kk + 3) * 33 + d];
            }
        }
        g_att_part[(((half * 8 + a) * 64 + p) * 8 + q) * 32 + d] = a0 + a1 + a2 + a3;
    }
}

// =================================================================
// Kernel 2b: combine the two k-halves into g_gl.
// =================================================================
__global__ __launch_bounds__(256)
void glimpse_combine_kernel()
{
    const int p = blockIdx.x >> 3, q = blockIdx.x & 7;
    const int t = threadIdx.x, a = t >> 5, d = t & 31;
    const int i0 = ((0 * 8 + a) * 64 + p) * 8 + q;
    const int i1 = ((1 * 8 + a) * 64 + p) * 8 + q;
    float2 ms0 = g_att_ms[i0];
    float2 ms1 = g_att_ms[i1];
    float m = fmaxf(ms0.x, ms1.x);
    float w0 = __expf(ms0.x - m), w1 = __expf(ms1.x - m);
    float den = ms0.y * w0 + ms1.y * w1;
    float P0 = g_att_part[i0 * 32 + d];
    float P1 = g_att_part[i1 * 32 + d];
    g_gl[(p * 8 + q) * 256 + a * 32 + d] = (P0 * w0 + P1 * w1) / den;
}

// =================================================================
// Kernel 3: qm = g_gl @ nn_O  (512x256 @ 256x256)
// =================================================================
__global__ __launch_bounds__(256)
void qm_kernel(const float* __restrict__ nn_O)
{
    __shared__ float A_s[32][33];
    __shared__ float B_s[32][33];
    const int t = threadIdx.x, tx = t & 31, ty = t >> 5;
    const int b0 = blockIdx.x * 32, j0 = blockIdx.y * 32;
    float acc[4] = {0, 0, 0, 0};
    for (int k0 = 0; k0 < 256; k0 += 32) {
        for (int i = t; i < 1024; i += 256) {
            int r = i >> 5, c = i & 31;
            A_s[r][c] = g_gl[(b0 + r) * 256 + k0 + c];
            B_s[r][c] = nn_O[(k0 + r) * 256 + j0 + c];
        }
        __syncthreads();
#pragma unroll
        for (int kk = 0; kk < 32; kk++) {
            float bv = B_s[kk][tx];
            acc[0] += A_s[ty][kk] * bv;
            acc[1] += A_s[ty + 8][kk] * bv;
            acc[2] += A_s[ty + 16][kk] * bv;
            acc[3] += A_s[ty + 24][kk] * bv;
        }
        __syncthreads();
    }
#pragma unroll
    for (int ri = 0; ri < 4; ri++)
        g_qm[(b0 + ty + 8 * ri) * 256 + j0 + tx] = acc[ri];
}

// =================================================================
// Kernel 4: logits.  block = (p, 25-k chunk) -> grid (64,20).
// =================================================================
__global__ __launch_bounds__(256)
void logits_kernel(const float* __restrict__ X, const float* __restrict__ varfeat,
                   const float* __restrict__ nn_A, const float* __restrict__ nn_B,
                   const float* __restrict__ nn_W)
{
    __shared__ __align__(16) float base_s[5][256];
    __shared__ float qm_s[8 * 256];
    __shared__ float vf_s[8][25];

    const int t  = threadIdx.x;
    const int p  = blockIdx.x;
    const int k0 = blockIdx.y * 25;

    for (int i = t; i < 2048; i += 256) qm_s[i] = g_qm[p * 8 * 256 + i];
    float a_v[8];
#pragma unroll
    for (int v = 0; v < 8; v++) a_v[v] = nn_A[v * 256 + t];
    const float bB = nn_B[t];
    for (int i = t; i < 200; i += 256) {
        int v = i / 25, kk = i - v * 25;
        vf_s[v][kk] = varfeat[(p * 8 + v) * NK + k0 + kk];
    }
    __syncthreads();

    const int w = t >> 5, l = t & 31;
    float qr[8], wr[8];
#pragma unroll
    for (int i = 0; i < 8; i++) {
        qr[i] = qm_s[w * 256 + l * 8 + i];
        wr[i] = nn_W[l * 8 + i];
    }

    for (int kt = 0; kt < 25; kt += 5) {
        // phase A: base = X + vf  (thread t owns h=t)
#pragma unroll
        for (int kk = 0; kk < 5; kk++) {
            int kg = k0 + kt + kk;
            float vf = bB;
#pragma unroll
            for (int v = 0; v < 8; v++) vf += vf_s[v][kt + kk] * a_v[v];
            base_s[kk][t] = X[(p * NK + kg) * 256 + t] + vf;
        }
        __syncthreads();
        // phase B: warp w handles q=w; lane covers 8 h values
#pragma unroll
        for (int kk = 0; kk < 5; kk++) {
            const float4* bp = (const float4*)&base_s[kk][0];
            float4 x0 = bp[l * 2], x1 = bp[l * 2 + 1];
            float s = fast_tanh(x0.x + qr[0]) * wr[0]
                    + fast_tanh(x0.y + qr[1]) * wr[1]
                    + fast_tanh(x0.z + qr[2]) * wr[2]
                    + fast_tanh(x0.w + qr[3]) * wr[3]
                    + fast_tanh(x1.x + qr[4]) * wr[4]
                    + fast_tanh(x1.y + qr[5]) * wr[5]
                    + fast_tanh(x1.z + qr[6]) * wr[6]
                    + fast_tanh(x1.w + qr[7]) * wr[7];
#pragma unroll
            for (int o = 16; o >= 1; o >>= 1) s += __shfl_xor_sync(0xffffffffu, s, o);
            if (l == 0) {
                int idx = (p * 8 + w) * NK + k0 + kt + kk;
                g_logit[idx] = g_mask[idx] ? -1e30f : s;
            }
        }
        __syncthreads();
    }
}

// =================================================================
// Kernel 5: choose.  chosen_p = -log(sum exp(l - max)) per row.
// Exact tanh here (error amplified x10 by CLIP).
// =================================================================
__global__ __launch_bounds__(128)
void choose_kernel(float* __restrict__ out_p)
{
    __shared__ float red[128];
    const int r = blockIdx.x, t = threadIdx.x;
    const float* row = g_logit + r * NK;

    float mx = -1e30f;
    for (int k = t; k < NK; k += 128) {
        float raw = row[k];
        if (raw > -1e29f) mx = fmaxf(mx, tanh_acc(raw) * 10.0f);
    }
    red[t] = mx; __syncthreads();
    for (int s = 64; s > 0; s >>= 1) {
        if (t < s) red[t] = fmaxf(red[t], red[t + s]);
        __syncthreads();
    }
    mx = red[0]; __syncthreads();

    float sm = 0.0f;
    for (int k = t; k < NK; k += 128) {
        float raw = row[k];
        if (raw > -1e29f) sm += __expf(tanh_acc(raw) * 10.0f - mx);
    }
    red[t] = sm; __syncthreads();
    for (int s = 64; s > 0; s >>= 1) {
        if (t < s) red[t] += red[t + s];
        __syncthreads();
    }
    if (t == 0) out_p[r] = -logf(red[0]);
}

// =================================================================
extern "C" void kernel_launch(void* const* d_in, const int* in_sizes, int n_in,
                              void* d_out, int out_size)
{
    const float* X       = (const float*)d_in[0];
    const float* Kt      = (const float*)d_in[1];
    const float* Vt      = (const float*)d_in[2];
    const float* query   = (const float*)d_in[3];
    const float* state1  = (const float*)d_in[4];
    const float* state2  = (const float*)d_in[5];
    const float* varfeat = (const float*)d_in[6];
    const void*  mask    = d_in[7];
    const float* nn_Q    = (const float*)d_in[8];
    const float* nn_O    = (const float*)d_in[9];
    const float* nn_A    = (const float*)d_in[10];
    const float* nn_B    = (const float*)d_in[11];
    const float* nn_W    = (const float*)d_in[12];
    const float* W_ih    = (const float*)d_in[13];
    const float* W_hh    = (const float*)d_in[14];
    const float* b_ih    = (const float*)d_in[15];
    const float* b_hh    = (const float*)d_in[16];

    float* out = (float*)d_out;
    float* out_h = out;                       // [512,256]
    float* out_c = out + 512 * 256;           // [512,256]
    float* out_p = out + 2 * 512 * 256;       // [512]

    detect_mask_kernel<<<1, 1024>>>((const unsigned int*)mask);
    normalize_mask_kernel<<<(BATCH * NK + 255) / 256, 256>>>(mask);
    lstm_part_kernel<<<dim3(16, 8, 2), 256>>>(query, state1, W_ih, W_hh);
    lstm_point_kernel<<<128, 256>>>(state2, b_ih, b_hh, out_h, out_c);
    glimpse_part_kernel<<<1024, 256>>>(out_h, Kt, Vt, nn_Q);
    glimpse_combine_kernel<<<512, 256>>>();
    qm_kernel<<<dim3(16, 8), 256>>>(nn_O);
    logits_kernel<<<dim3(64, 20), 256>>>(X, varfeat, nn_A, nn_B, nn_W);
    choose_kernel<<<512, 128>>>(out_p);
}

// round 5
// speedup vs baseline: 1.3794x; 1.0127x over previous
#include <cuda_runtime.h>
#include <math.h>

#define NPROB  64
#define NRR    8
#define NK     500
#define HDIM   256
#define NHEADS 8
#define HD     32
#define BATCH  512   // NPROB*NRR
#define KHALF  250   // NK / 2 k-split for glimpse

// ---------------- scratch (no allocations allowed) ----------------
__device__ float g_gl[BATCH * HDIM];       // glimpse (concat heads), [b][H]
__device__ float g_qm[BATCH * HDIM];       // glimpse @ nn_O
__device__ float g_logit[BATCH * NK];      // masked logits (-1e30 sentinel)
__device__ int   g_mask_mode;              // 0=u8,1=i32,2=f32,3=bf16
__device__ unsigned char g_mask[BATCH * NK];
__device__ float g_att_part[2 * NHEADS * NPROB * NRR * HD];  // [half][a][p][q][d]
__device__ float2 g_att_ms[2 * NHEADS * NPROB * NRR];        // (max, sumexp)

// single-instruction MUFU.TANH (abs err ~2^-10.6) -- hot path only
__device__ __forceinline__ float fast_tanh(float x) {
    float y;
    asm("tanh.approx.f32 %0, %1;" : "=f"(y) : "f"(x));
    return y;
}
// exact tanh: 1 - 2/(exp(2x)+1)
__device__ __forceinline__ float tanh_acc(float x) {
    float e = __expf(2.0f * x);
    return 1.0f - __fdividef(2.0f, e + 1.0f);
}
__device__ __forceinline__ float sigmoidf_(float x) {
    return 1.0f / (1.0f + __expf(-x));
}

// =================================================================
// Kernel 0a: detect mask dtype from raw bits.
// =================================================================
__global__ void detect_mask_kernel(const unsigned int* __restrict__ mraw)
{
    __shared__ int s_i32, s_f32, s_bf16;
    const int t = threadIdx.x;
    if (t == 0) { s_i32 = 1; s_f32 = 1; s_bf16 = 1; }
    __syncthreads();
    int ok_i32 = 1, ok_f32 = 1, ok_bf16 = 1;
    for (int i = t; i < 8000; i += blockDim.x) {
        unsigned int w = mraw[i];
        ok_i32  &= (w <= 1u);
        ok_f32  &= (w == 0u || w == 0x3F800000u);
        unsigned int lo = w & 0xFFFFu, hi = w >> 16;
        ok_bf16 &= (lo == 0u || lo == 0x3F80u) && (hi == 0u || hi == 0x3F80u);
    }
    if (!ok_i32)  atomicAnd(&s_i32, 0);
    if (!ok_f32)  atomicAnd(&s_f32, 0);
    if (!ok_bf16) atomicAnd(&s_bf16, 0);
    __syncthreads();
    if (t == 0) {
        int mode = 0;
        if (s_i32) mode = 1;
        else if (s_f32) mode = 2;
        else if (s_bf16) mode = 3;
        g_mask_mode = mode;
    }
}

// =================================================================
// Kernel 0b: normalize mask to bytes in g_mask
// =================================================================
__global__ void normalize_mask_kernel(const void* __restrict__ mraw)
{
    const int idx = blockIdx.x * blockDim.x + threadIdx.x;
    if (idx >= BATCH * NK) return;
    const int mode = g_mask_mode;
    unsigned char v;
    if (mode == 1)      v = (((const int*)mraw)[idx] != 0);
    else if (mode == 2) v = (((const unsigned int*)mraw)[idx] != 0u);
    else if (mode == 3) v = (((const unsigned short*)mraw)[idx] != 0u);
    else                v = (((const unsigned char*)mraw)[idx] != 0u);
    g_mask[idx] = v;
}

// =================================================================
// Kernel 1: fused LSTM.  gates = [query|state1] @ [W_ih|W_hh]^T + b,
// pointwise epilogue in-block (each block owns full gate set for its
// 32b x 32j tile).
// =================================================================
__global__ __launch_bounds__(256)
void lstm_kernel(const float* __restrict__ query, const float* __restrict__ state1,
                 const float* __restrict__ state2,
                 const float* __restrict__ W_ih, const float* __restrict__ W_hh,
                 const float* __restrict__ b_ih, const float* __restrict__ b_hh,
                 float* __restrict__ out_h, float* __restrict__ out_c)
{
    __shared__ float A_s[32][33];
    __shared__ float W_s[4][32][33];
    const int t  = threadIdx.x;
    const int tx = t & 31, ty = t >> 5;      // ty 0..7
    const int b0 = blockIdx.x * 32, j0 = blockIdx.y * 32;
    const int lrow = t >> 3, lk = (t & 7) * 4;

    float acc[4][4];
#pragma unroll
    for (int i = 0; i < 4; i++)
#pragma unroll
        for (int j = 0; j < 4; j++) acc[i][j] = 0.0f;

    for (int k0 = 0; k0 < 512; k0 += 32) {
        const float* Asrc = (k0 < 256) ? (query + k0) : (state1 + (k0 - 256));
        const float* Wsrc = (k0 < 256) ? (W_ih + k0)  : (W_hh  + (k0 - 256));
        float4 av = *(const float4*)&Asrc[(b0 + lrow) * 256 + lk];
        A_s[lrow][lk + 0] = av.x; A_s[lrow][lk + 1] = av.y;
        A_s[lrow][lk + 2] = av.z; A_s[lrow][lk + 3] = av.w;
#pragma unroll
        for (int gg = 0; gg < 4; gg++) {
            float4 wv = *(const float4*)&Wsrc[(gg * 256 + j0 + lrow) * 256 + lk];
            W_s[gg][lrow][lk + 0] = wv.x; W_s[gg][lrow][lk + 1] = wv.y;
            W_s[gg][lrow][lk + 2] = wv.z; W_s[gg][lrow][lk + 3] = wv.w;
        }
        __syncthreads();
#pragma unroll
        for (int kk = 0; kk < 32; kk++) {
            float a0 = A_s[ty][kk], a1 = A_s[ty + 8][kk];
            float a2 = A_s[ty + 16][kk], a3 = A_s[ty + 24][kk];
            float w0 = W_s[0][tx][kk], w1 = W_s[1][tx][kk];
            float w2 = W_s[2][tx][kk], w3 = W_s[3][tx][kk];
            acc[0][0] += a0 * w0; acc[0][1] += a0 * w1; acc[0][2] += a0 * w2; acc[0][3] += a0 * w3;
            acc[1][0] += a1 * w0; acc[1][1] += a1 * w1; acc[1][2] += a1 * w2; acc[1][3] += a1 * w3;
            acc[2][0] += a2 * w0; acc[2][1] += a2 * w1; acc[2][2] += a2 * w2; acc[2][3] += a2 * w3;
            acc[3][0] += a3 * w0; acc[3][1] += a3 * w1; acc[3][2] += a3 * w2; acc[3][3] += a3 * w3;
        }
        __syncthreads();
    }

    const int j = j0 + tx;
    const float bias0 = b_ih[j]       + b_hh[j];
    const float bias1 = b_ih[256 + j] + b_hh[256 + j];
    const float bias2 = b_ih[512 + j] + b_hh[512 + j];
    const float bias3 = b_ih[768 + j] + b_hh[768 + j];
#pragma unroll
    for (int ri = 0; ri < 4; ri++) {
        const int b = b0 + ty + 8 * ri;
        float ig = sigmoidf_(acc[ri][0] + bias0);
        float fg = sigmoidf_(acc[ri][1] + bias1);
        float gg = tanh_acc(acc[ri][2] + bias2);
        float og = sigmoidf_(acc[ri][3] + bias3);
        float c  = fg * state2[b * 256 + j] + ig * gg;
        float h  = og * tanh_acc(c);
        out_h[b * 256 + j] = h;
        out_c[b * 256 + j] = c;
    }
}

// =================================================================
// Kernel 2a: glimpse attention partials.  block = (half, head a, problem p).
// =================================================================
__global__ __launch_bounds__(256)
void glimpse_part_kernel(const float* __restrict__ h_in, const float* __restrict__ Kt,
                         const float* __restrict__ Vt, const float* __restrict__ nn_Q)
{
    __shared__ float q_s[8 * 256];
    __shared__ __align__(16) float Q_s[8 * 32];
    __shared__ float S_s[8 * 256];
    __shared__ float K_s[64 * 33];

    const int t = threadIdx.x;
    const int half = blockIdx.x >> 9;
    const int a = (blockIdx.x >> 6) & 7;
    const int p = blockIdx.x & 63;
    const int kb = (a * 64 + p) * NK * HD;
    const int kbase = half * KHALF;

    // 1. stage q
    for (int i = t; i < 2048; i += 256) q_s[i] = h_in[p * 8 * 256 + i];
    __syncthreads();

    // 2. Q = q @ nn_Q[a] * 1/sqrt(HD)
    {
        const int q = t >> 5, d = t & 31;
        const float* qn = nn_Q + a * 256 * 32 + d;
        const float* qr = q_s + q * 256;
        float s0 = 0, s1 = 0, s2 = 0, s3 = 0;
#pragma unroll 4
        for (int hh = 0; hh < 256; hh += 4) {
            s0 += qr[hh + 0] * qn[(hh + 0) * 32];
            s1 += qr[hh + 1] * qn[(hh + 1) * 32];
            s2 += qr[hh + 2] * qn[(hh + 2) * 32];
            s3 += qr[hh + 3] * qn[(hh + 3) * 32];
        }
        Q_s[q * 32 + d] = (s0 + s1 + s2 + s3) * 0.17677669529663687f;
    }
    __syncthreads();

    // 3. S = Q K^T (masked), staged K chunks of 64 rows (250 keys)
    const int kloc = t & 63, qp = t >> 6;
    const int q0 = qp * 2, q1 = q0 + 1;
    for (int c0 = 0; c0 < KHALF; c0 += 64) {
        for (int i = t; i < 2048; i += 256) {
            int row = i >> 5, d = i & 31;
            if (c0 + row < KHALF)
                K_s[row * 33 + d] = Kt[kb + (kbase + c0 + row) * 32 + d];
        }
        __syncthreads();
        int kl = c0 + kloc;
        if (kl < KHALF) {
            int kg = kbase + kl;
            float acc0 = 0, acc1 = 0;
            const float4* Qs4 = (const float4*)Q_s;
#pragma unroll
            for (int d4 = 0; d4 < 8; d4++) {
                float4 qa = Qs4[q0 * 8 + d4];
                float4 qb = Qs4[q1 * 8 + d4];
                int kbs = kloc * 33 + d4 * 4;
                float k0v = K_s[kbs], k1v = K_s[kbs + 1];
                float k2v = K_s[kbs + 2], k3v = K_s[kbs + 3];
                acc0 += k0v * qa.x + k1v * qa.y + k2v * qa.z + k3v * qa.w;
                acc1 += k0v * qb.x + k1v * qb.y + k2v * qb.z + k3v * qb.w;
            }
            S_s[q0 * 256 + kl] = g_mask[(p * 8 + q0) * NK + kg] ? -1e30f : acc0;
            S_s[q1 * 256 + kl] = g_mask[(p * 8 + q1) * NK + kg] ? -1e30f : acc1;
        }
        __syncthreads();
    }

    // 4. partial softmax stats per q (warp w -> q = w)
    {
        const int w = t >> 5, l = t & 31;
        float mx = -1e30f;
        for (int k = l; k < KHALF; k += 32) mx = fmaxf(mx, S_s[w * 256 + k]);
#pragma unroll
        for (int o = 16; o >= 1; o >>= 1) mx = fmaxf(mx, __shfl_xor_sync(0xffffffffu, mx, o));
        float sm = 0;
        for (int k = l; k < KHALF; k += 32) {
            float e = __expf(S_s[w * 256 + k] - mx);
            S_s[w * 256 + k] = e;
            sm += e;
        }
#pragma unroll
        for (int o = 16; o >= 1; o >>= 1) sm += __shfl_xor_sync(0xffffffffu, sm, o);
        if (l == 0)
            g_att_ms[((half * 8 + a) * 64 + p) * 8 + w] = make_float2(mx, sm);
    }
    __syncthreads();

    // 5. partial (unnormalized) x = S V, direct from global with 5-way MLP
    {
        const int q = t >> 5, d = t & 31;
        const float* vp = Vt + kb + kbase * 32 + d;
        const float* sp = S_s + q * 256;
        float a0 = 0, a1 = 0, a2 = 0, a3 = 0, a4 = 0;
#pragma unroll 10
        for (int k = 0; k < KHALF; k += 5) {
            a0 += sp[k + 0] * vp[(k + 0) * 32];
            a1 += sp[k + 1] * vp[(k + 1) * 32];
            a2 += sp[k + 2] * vp[(k + 2) * 32];
            a3 += sp[k + 3] * vp[(k + 3) * 32];
            a4 += sp[k + 4] * vp[(k + 4) * 32];
        }
        g_att_part[(((half * 8 + a) * 64 + p) * 8 + q) * 32 + d] = a0 + a1 + a2 + a3 + a4;
    }
}

// =================================================================
// Kernel 2b: combine the two k-halves into g_gl.
// =================================================================
__global__ __launch_bounds__(256)
void glimpse_combine_kernel()
{
    const int p = blockIdx.x >> 3, q = blockIdx.x & 7;
    const int t = threadIdx.x, a = t >> 5, d = t & 31;
    const int i0 = ((0 * 8 + a) * 64 + p) * 8 + q;
    const int i1 = ((1 * 8 + a) * 64 + p) * 8 + q;
    float2 ms0 = g_att_ms[i0];
    float2 ms1 = g_att_ms[i1];
    float m = fmaxf(ms0.x, ms1.x);
    float w0 = __expf(ms0.x - m), w1 = __expf(ms1.x - m);
    float den = ms0.y * w0 + ms1.y * w1;
    float P0 = g_att_part[i0 * 32 + d];
    float P1 = g_att_part[i1 * 32 + d];
    g_gl[(p * 8 + q) * 256 + a * 32 + d] = (P0 * w0 + P1 * w1) / den;
}

// =================================================================
// Kernel 3: qm = g_gl @ nn_O  (512x256 @ 256x256)
// =================================================================
__global__ __launch_bounds__(256)
void qm_kernel(const float* __restrict__ nn_O)
{
    __shared__ float A_s[32][33];
    __shared__ float B_s[32][33];
    const int t = threadIdx.x, tx = t & 31, ty = t >> 5;
    const int b0 = blockIdx.x * 32, j0 = blockIdx.y * 32;
    float acc[4] = {0, 0, 0, 0};
    for (int k0 = 0; k0 < 256; k0 += 32) {
        for (int i = t; i < 1024; i += 256) {
            int r = i >> 5, c = i & 31;
            A_s[r][c] = g_gl[(b0 + r) * 256 + k0 + c];
            B_s[r][c] = nn_O[(k0 + r) * 256 + j0 + c];
        }
        __syncthreads();
#pragma unroll
        for (int kk = 0; kk < 32; kk++) {
            float bv = B_s[kk][tx];
            acc[0] += A_s[ty][kk] * bv;
            acc[1] += A_s[ty + 8][kk] * bv;
            acc[2] += A_s[ty + 16][kk] * bv;
            acc[3] += A_s[ty + 24][kk] * bv;
        }
        __syncthreads();
    }
#pragma unroll
    for (int ri = 0; ri < 4; ri++)
        g_qm[(b0 + ty + 8 * ri) * 256 + j0 + tx] = acc[ri];
}

// =================================================================
// Kernel 4: logits, shuffle-free.  block = (p, 32-k chunk), grid (64,16).
// phase A: base_s[h][k] = X + vf (transposed).  phase B: warp=q, lane=k,
// each thread privately reduces over all 256 h.  2 syncs, 0 shuffles.
// =================================================================
__global__ __launch_bounds__(256)
void logits_kernel(const float* __restrict__ X, const float* __restrict__ varfeat,
                   const float* __restrict__ nn_A, const float* __restrict__ nn_B,
                   const float* __restrict__ nn_W)
{
    __shared__ float base_s[256][33];   // [h][k] padded
    __shared__ float qm_s[8 * 256];
    __shared__ float w_s[256];
    __shared__ float vf_s[8][32];

    const int t  = threadIdx.x;
    const int p  = blockIdx.x;
    const int k0 = blockIdx.y * 32;

    for (int i = t; i < 2048; i += 256) qm_s[i] = g_qm[p * 8 * 256 + i];
    w_s[t] = nn_W[t];
    float a_v[8];
#pragma unroll
    for (int v = 0; v < 8; v++) a_v[v] = nn_A[v * 256 + t];
    const float bB = nn_B[t];
    if (t < 256) {
        int v = t >> 5, kk = t & 31;
        vf_s[v][kk] = (k0 + kk < NK) ? varfeat[(p * 8 + v) * NK + k0 + kk] : 0.0f;
    }
    __syncthreads();

    // phase A: thread t owns h = t, loops 32 k's
#pragma unroll 8
    for (int kk = 0; kk < 32; kk++) {
        int kg = k0 + kk;
        float vf = bB;
#pragma unroll
        for (int v = 0; v < 8; v++) vf += vf_s[v][kk] * a_v[v];
        float xv = (kg < NK) ? X[(p * NK + kg) * 256 + t] : 0.0f;
        base_s[t][kk] = xv + vf;
    }
    __syncthreads();

    // phase B: warp w = q, lane l = k; private 256-h reduction
    {
        const int w = t >> 5, l = t & 31;
        const int kg = k0 + l;
        const float* qmr = qm_s + w * 256;
        float a0 = 0, a1 = 0, a2 = 0, a3 = 0;
#pragma unroll 16
        for (int h = 0; h < 256; h += 4) {
            a0 += w_s[h + 0] * fast_tanh(base_s[h + 0][l] + qmr[h + 0]);
            a1 += w_s[h + 1] * fast_tanh(base_s[h + 1][l] + qmr[h + 1]);
            a2 += w_s[h + 2] * fast_tanh(base_s[h + 2][l] + qmr[h + 2]);
            a3 += w_s[h + 3] * fast_tanh(base_s[h + 3][l] + qmr[h + 3]);
        }
        if (kg < NK) {
            int idx = (p * 8 + w) * NK + kg;
            g_logit[idx] = g_mask[idx] ? -1e30f : (a0 + a1) + (a2 + a3);
        }
    }
}

// =================================================================
// Kernel 5: choose.  chosen_p = -log(sum exp(l - max)) per row.
// Exact tanh here (error amplified x10 by CLIP).
// =================================================================
__global__ __launch_bounds__(128)
void choose_kernel(float* __restrict__ out_p)
{
    __shared__ float red[128];
    const int r = blockIdx.x, t = threadIdx.x;
    const float* row = g_logit + r * NK;

    float mx = -1e30f;
    for (int k = t; k < NK; k += 128) {
        float raw = row[k];
        if (raw > -1e29f) mx = fmaxf(mx, tanh_acc(raw) * 10.0f);
    }
    red[t] = mx; __syncthreads();
    for (int s = 64; s > 0; s >>= 1) {
        if (t < s) red[t] = fmaxf(red[t], red[t + s]);
        __syncthreads();
    }
    mx = red[0]; __syncthreads();

    float sm = 0.0f;
    for (int k = t; k < NK; k += 128) {
        float raw = row[k];
        if (raw > -1e29f) sm += __expf(tanh_acc(raw) * 10.0f - mx);
    }
    red[t] = sm; __syncthreads();
    for (int s = 64; s > 0; s >>= 1) {
        if (t < s) red[t] += red[t + s];
        __syncthreads();
    }
    if (t == 0) out_p[r] = -logf(red[0]);
}

// =================================================================
extern "C" void kernel_launch(void* const* d_in, const int* in_sizes, int n_in,
                              void* d_out, int out_size)
{
    const float* X       = (const float*)d_in[0];
    const float* Kt      = (const float*)d_in[1];
    const float* Vt      = (const float*)d_in[2];
    const float* query   = (const float*)d_in[3];
    const float* state1  = (const float*)d_in[4];
    const float* state2  = (const float*)d_in[5];
    const float* varfeat = (const float*)d_in[6];
    const void*  mask    = d_in[7];
    const float* nn_Q    = (const float*)d_in[8];
    const float* nn_O    = (const float*)d_in[9];
    const float* nn_A    = (const float*)d_in[10];
    const float* nn_B    = (const float*)d_in[11];
    const float* nn_W    = (const float*)d_in[12];
    const float* W_ih    = (const float*)d_in[13];
    const float* W_hh    = (const float*)d_in[14];
    const float* b_ih    = (const float*)d_in[15];
    const float* b_hh    = (const float*)d_in[16];

    float* out = (float*)d_out;
    float* out_h = out;                       // [512,256]
    float* out_c = out + 512 * 256;           // [512,256]
    float* out_p = out + 2 * 512 * 256;       // [512]

    detect_mask_kernel<<<1, 1024>>>((const unsigned int*)mask);
    normalize_mask_kernel<<<(BATCH * NK + 255) / 256, 256>>>(mask);
    lstm_kernel<<<dim3(16, 8), 256>>>(query, state1, state2, W_ih, W_hh,
                                      b_ih, b_hh, out_h, out_c);
    glimpse_part_kernel<<<1024, 256>>>(out_h, Kt, Vt, nn_Q);
    glimpse_combine_kernel<<<512, 256>>>();
    qm_kernel<<<dim3(16, 8), 256>>>(nn_O);
    logits_kernel<<<dim3(64, 16), 256>>>(X, varfeat, nn_A, nn_B, nn_W);
    choose_kernel<<<512, 128>>>(out_p);
}

// round 6
// speedup vs baseline: 1.3909x; 1.0084x over previous
#include <cuda_runtime.h>
#include <math.h>

#define NPROB  64
#define NRR    8
#define NK     500
#define HDIM   256
#define NHEADS 8
#define HD     32
#define BATCH  512   // NPROB*NRR
#define KQ     125   // NK / 4 k-split for glimpse
#define NSPLIT 4

// ---------------- scratch (no allocations allowed) ----------------
__device__ float g_gl[BATCH * HDIM];       // glimpse (concat heads), [b][H]
__device__ float g_qm[BATCH * HDIM];       // glimpse @ nn_O
__device__ float g_Q[NHEADS * BATCH * HD]; // projected queries [a][pq][d]
__device__ float g_logit[BATCH * NK];      // masked logits (-1e30 sentinel)
__device__ int   g_mask_mode;              // 0=u8,1=i32,2=f32,3=bf16
__device__ unsigned char g_mask[BATCH * NK];
__device__ float g_att_part[NSPLIT * NHEADS * NPROB * NRR * HD];
__device__ float2 g_att_ms[NSPLIT * NHEADS * NPROB * NRR];

// single-instruction MUFU.TANH (abs err ~2^-10.6) -- hot path only
__device__ __forceinline__ float fast_tanh(float x) {
    float y;
    asm("tanh.approx.f32 %0, %1;" : "=f"(y) : "f"(x));
    return y;
}
// exact tanh: 1 - 2/(exp(2x)+1)
__device__ __forceinline__ float tanh_acc(float x) {
    float e = __expf(2.0f * x);
    return 1.0f - __fdividef(2.0f, e + 1.0f);
}
__device__ __forceinline__ float sigmoidf_(float x) {
    return 1.0f / (1.0f + __expf(-x));
}

// =================================================================
// Kernel 0a: detect mask dtype from raw bits.
// =================================================================
__global__ void detect_mask_kernel(const unsigned int* __restrict__ mraw)
{
    __shared__ int s_i32, s_f32, s_bf16;
    const int t = threadIdx.x;
    if (t == 0) { s_i32 = 1; s_f32 = 1; s_bf16 = 1; }
    __syncthreads();
    int ok_i32 = 1, ok_f32 = 1, ok_bf16 = 1;
    for (int i = t; i < 8000; i += blockDim.x) {
        unsigned int w = mraw[i];
        ok_i32  &= (w <= 1u);
        ok_f32  &= (w == 0u || w == 0x3F800000u);
        unsigned int lo = w & 0xFFFFu, hi = w >> 16;
        ok_bf16 &= (lo == 0u || lo == 0x3F80u) && (hi == 0u || hi == 0x3F80u);
    }
    if (!ok_i32)  atomicAnd(&s_i32, 0);
    if (!ok_f32)  atomicAnd(&s_f32, 0);
    if (!ok_bf16) atomicAnd(&s_bf16, 0);
    __syncthreads();
    if (t == 0) {
        int mode = 0;
        if (s_i32) mode = 1;
        else if (s_f32) mode = 2;
        else if (s_bf16) mode = 3;
        g_mask_mode = mode;
    }
}

// =================================================================
// Kernel 0b: normalize mask to bytes in g_mask
// =================================================================
__global__ void normalize_mask_kernel(const void* __restrict__ mraw)
{
    const int idx = blockIdx.x * blockDim.x + threadIdx.x;
    if (idx >= BATCH * NK) return;
    const int mode = g_mask_mode;
    unsigned char v;
    if (mode == 1)      v = (((const int*)mraw)[idx] != 0);
    else if (mode == 2) v = (((const unsigned int*)mraw)[idx] != 0u);
    else if (mode == 3) v = (((const unsigned short*)mraw)[idx] != 0u);
    else                v = (((const unsigned char*)mraw)[idx] != 0u);
    g_mask[idx] = v;
}

// =================================================================
// Kernel 1: fused LSTM.
// =================================================================
__global__ __launch_bounds__(256)
void lstm_kernel(const float* __restrict__ query, const float* __restrict__ state1,
                 const float* __restrict__ state2,
                 const float* __restrict__ W_ih, const float* __restrict__ W_hh,
                 const float* __restrict__ b_ih, const float* __restrict__ b_hh,
                 float* __restrict__ out_h, float* __restrict__ out_c)
{
    __shared__ float A_s[32][33];
    __shared__ float W_s[4][32][33];
    const int t  = threadIdx.x;
    const int tx = t & 31, ty = t >> 5;
    const int b0 = blockIdx.x * 32, j0 = blockIdx.y * 32;
    const int lrow = t >> 3, lk = (t & 7) * 4;

    float acc[4][4];
#pragma unroll
    for (int i = 0; i < 4; i++)
#pragma unroll
        for (int j = 0; j < 4; j++) acc[i][j] = 0.0f;

    for (int k0 = 0; k0 < 512; k0 += 32) {
        const float* Asrc = (k0 < 256) ? (query + k0) : (state1 + (k0 - 256));
        const float* Wsrc = (k0 < 256) ? (W_ih + k0)  : (W_hh  + (k0 - 256));
        float4 av = *(const float4*)&Asrc[(b0 + lrow) * 256 + lk];
        A_s[lrow][lk + 0] = av.x; A_s[lrow][lk + 1] = av.y;
        A_s[lrow][lk + 2] = av.z; A_s[lrow][lk + 3] = av.w;
#pragma unroll
        for (int gg = 0; gg < 4; gg++) {
            float4 wv = *(const float4*)&Wsrc[(gg * 256 + j0 + lrow) * 256 + lk];
            W_s[gg][lrow][lk + 0] = wv.x; W_s[gg][lrow][lk + 1] = wv.y;
            W_s[gg][lrow][lk + 2] = wv.z; W_s[gg][lrow][lk + 3] = wv.w;
        }
        __syncthreads();
#pragma unroll
        for (int kk = 0; kk < 32; kk++) {
            float a0 = A_s[ty][kk], a1 = A_s[ty + 8][kk];
            float a2 = A_s[ty + 16][kk], a3 = A_s[ty + 24][kk];
            float w0 = W_s[0][tx][kk], w1 = W_s[1][tx][kk];
            float w2 = W_s[2][tx][kk], w3 = W_s[3][tx][kk];
            acc[0][0] += a0 * w0; acc[0][1] += a0 * w1; acc[0][2] += a0 * w2; acc[0][3] += a0 * w3;
            acc[1][0] += a1 * w0; acc[1][1] += a1 * w1; acc[1][2] += a1 * w2; acc[1][3] += a1 * w3;
            acc[2][0] += a2 * w0; acc[2][1] += a2 * w1; acc[2][2] += a2 * w2; acc[2][3] += a2 * w3;
            acc[3][0] += a3 * w0; acc[3][1] += a3 * w1; acc[3][2] += a3 * w2; acc[3][3] += a3 * w3;
        }
        __syncthreads();
    }

    const int j = j0 + tx;
    const float bias0 = b_ih[j]       + b_hh[j];
    const float bias1 = b_ih[256 + j] + b_hh[256 + j];
    const float bias2 = b_ih[512 + j] + b_hh[512 + j];
    const float bias3 = b_ih[768 + j] + b_hh[768 + j];
#pragma unroll
    for (int ri = 0; ri < 4; ri++) {
        const int b = b0 + ty + 8 * ri;
        float ig = sigmoidf_(acc[ri][0] + bias0);
        float fg = sigmoidf_(acc[ri][1] + bias1);
        float gg = tanh_acc(acc[ri][2] + bias2);
        float og = sigmoidf_(acc[ri][3] + bias3);
        float c  = fg * state2[b * 256 + j] + ig * gg;
        float h  = og * tanh_acc(c);
        out_h[b * 256 + j] = h;
        out_c[b * 256 + j] = c;
    }
}

// =================================================================
// Kernel 1.5: qproj.  g_Q[a][pq][d] = (h @ nn_Q[a]) * 1/sqrt(HD).
// grid (16 pq-tiles, 8 heads).
// =================================================================
__global__ __launch_bounds__(256)
void qproj_kernel(const float* __restrict__ h_in, const float* __restrict__ nn_Q)
{
    __shared__ float A_s[32][33];
    __shared__ float B_s[32][33];
    const int t = threadIdx.x, tx = t & 31, ty = t >> 5;
    const int r0 = blockIdx.x * 32;
    const int a  = blockIdx.y;
    float acc[4] = {0, 0, 0, 0};
    for (int k0 = 0; k0 < 256; k0 += 32) {
        for (int i = t; i < 1024; i += 256) {
            int r = i >> 5, c = i & 31;
            A_s[r][c] = h_in[(r0 + r) * 256 + k0 + c];
            B_s[r][c] = nn_Q[a * 8192 + (k0 + r) * 32 + c];
        }
        __syncthreads();
#pragma unroll
        for (int kk = 0; kk < 32; kk++) {
            float bv = B_s[kk][tx];
            acc[0] += A_s[ty][kk] * bv;
            acc[1] += A_s[ty + 8][kk] * bv;
            acc[2] += A_s[ty + 16][kk] * bv;
            acc[3] += A_s[ty + 24][kk] * bv;
        }
        __syncthreads();
    }
#pragma unroll
    for (int ri = 0; ri < 4; ri++)
        g_Q[(a * 512 + r0 + ty + 8 * ri) * 32 + tx] = acc[ri] * 0.17677669529663687f;
}

// =================================================================
// Kernel 2a: glimpse partials.  block = (quarter, head a, problem p),
// grid 2048.  Q preprojected; K and V staged through smem.
// =================================================================
__global__ __launch_bounds__(256)
void glimpse_part_kernel(const float* __restrict__ Kt, const float* __restrict__ Vt)
{
    __shared__ __align__(16) float Q_s[8 * 32];
    __shared__ float S_s[8 * 128];
    __shared__ float K_s[64 * 33];

    const int t = threadIdx.x;
    const int quarter = blockIdx.x >> 9;
    const int a = (blockIdx.x >> 6) & 7;
    const int p = blockIdx.x & 63;
    const int kb = (a * 64 + p) * NK * HD;
    const int kbase = quarter * KQ;

    // 1. load preprojected Q (256 contiguous floats)
    Q_s[t] = g_Q[(a * 512 + p * 8) * 32 + t];
    __syncthreads();

    // 2. S = Q K^T (masked), K staged in 64-row chunks (125 keys)
    const int kloc = t & 63, qp = t >> 6;
    const int q0 = qp * 2, q1 = q0 + 1;
#pragma unroll
    for (int c0 = 0; c0 < KQ; c0 += 64) {
        for (int i = t; i < 2048; i += 256) {
            int row = i >> 5, d = i & 31;
            if (c0 + row < KQ)
                K_s[row * 33 + d] = Kt[kb + (kbase + c0 + row) * 32 + d];
        }
        __syncthreads();
        int kl = c0 + kloc;
        if (kl < KQ) {
            int kg = kbase + kl;
            float acc0 = 0, acc1 = 0;
            const float4* Qs4 = (const float4*)Q_s;
#pragma unroll
            for (int d4 = 0; d4 < 8; d4++) {
                float4 qa = Qs4[q0 * 8 + d4];
                float4 qb = Qs4[q1 * 8 + d4];
                int kbs = kloc * 33 + d4 * 4;
                float k0v = K_s[kbs], k1v = K_s[kbs + 1];
                float k2v = K_s[kbs + 2], k3v = K_s[kbs + 3];
                acc0 += k0v * qa.x + k1v * qa.y + k2v * qa.z + k3v * qa.w;
                acc1 += k0v * qb.x + k1v * qb.y + k2v * qb.z + k3v * qb.w;
            }
            S_s[q0 * 128 + kl] = g_mask[(p * 8 + q0) * NK + kg] ? -1e30f : acc0;
            S_s[q1 * 128 + kl] = g_mask[(p * 8 + q1) * NK + kg] ? -1e30f : acc1;
        }
        __syncthreads();
    }

    // 3. partial softmax stats per q (warp w -> q = w); zero pad [125,128)
    {
        const int w = t >> 5, l = t & 31;
        float mx = -1e30f;
        for (int k = l; k < KQ; k += 32) mx = fmaxf(mx, S_s[w * 128 + k]);
#pragma unroll
        for (int o = 16; o >= 1; o >>= 1) mx = fmaxf(mx, __shfl_xor_sync(0xffffffffu, mx, o));
        float sm = 0;
        for (int k = l; k < KQ; k += 32) {
            float e = __expf(S_s[w * 128 + k] - mx);
            S_s[w * 128 + k] = e;
            sm += e;
        }
#pragma unroll
        for (int o = 16; o >= 1; o >>= 1) sm += __shfl_xor_sync(0xffffffffu, sm, o);
        if (l == 0)
            g_att_ms[((quarter * 8 + a) * 64 + p) * 8 + w] = make_float2(mx, sm);
        for (int k = KQ + l; k < 128; k += 32) S_s[w * 128 + k] = 0.0f;
    }

    // 4. partial (unnormalized) x = S V, V staged through smem (kills 8x
    // warp-redundant global reads)
    {
        const int q = t >> 5, d = t & 31;
        float a0 = 0, a1 = 0, a2 = 0, a3 = 0;
#pragma unroll
        for (int c0 = 0; c0 < 128; c0 += 64) {
            __syncthreads();
            for (int i = t; i < 2048; i += 256) {
                int row = i >> 5, dd = i & 31;
                K_s[row * 33 + dd] = (c0 + row < KQ)
                    ? Vt[kb + (kbase + c0 + row) * 32 + dd] : 0.0f;
            }
            __syncthreads();
            const float* sp = S_s + q * 128 + c0;
#pragma unroll
            for (int kk = 0; kk < 64; kk += 4) {
                a0 += sp[kk + 0] * K_s[(kk + 0) * 33 + d];
                a1 += sp[kk + 1] * K_s[(kk + 1) * 33 + d];
                a2 += sp[kk + 2] * K_s[(kk + 2) * 33 + d];
                a3 += sp[kk + 3] * K_s[(kk + 3) * 33 + d];
            }
        }
        g_att_part[(((quarter * 8 + a) * 64 + p) * 8 + q) * 32 + d] = (a0 + a1) + (a2 + a3);
    }
}

// =================================================================
// Kernel 2b: combine the four k-quarters into g_gl.
// =================================================================
__global__ __launch_bounds__(256)
void glimpse_combine_kernel()
{
    const int p = blockIdx.x >> 3, q = blockIdx.x & 7;
    const int t = threadIdx.x, a = t >> 5, d = t & 31;
    int idx[NSPLIT];
    float2 ms[NSPLIT];
    float m = -1e30f;
#pragma unroll
    for (int i = 0; i < NSPLIT; i++) {
        idx[i] = ((i * 8 + a) * 64 + p) * 8 + q;
        ms[i] = g_att_ms[idx[i]];
        m = fmaxf(m, ms[i].x);
    }
    float den = 0.0f, num = 0.0f;
#pragma unroll
    for (int i = 0; i < NSPLIT; i++) {
        float w = __expf(ms[i].x - m);
        den += ms[i].y * w;
        num += g_att_part[idx[i] * 32 + d] * w;
    }
    g_gl[(p * 8 + q) * 256 + a * 32 + d] = num / den;
}

// =================================================================
// Kernel 3: qm = g_gl @ nn_O  (512x256 @ 256x256)
// =================================================================
__global__ __launch_bounds__(256)
void qm_kernel(const float* __restrict__ nn_O)
{
    __shared__ float A_s[32][33];
    __shared__ float B_s[32][33];
    const int t = threadIdx.x, tx = t & 31, ty = t >> 5;
    const int b0 = blockIdx.x * 32, j0 = blockIdx.y * 32;
    float acc[4] = {0, 0, 0, 0};
    for (int k0 = 0; k0 < 256; k0 += 32) {
        for (int i = t; i < 1024; i += 256) {
            int r = i >> 5, c = i & 31;
            A_s[r][c] = g_gl[(b0 + r) * 256 + k0 + c];
            B_s[r][c] = nn_O[(k0 + r) * 256 + j0 + c];
        }
        __syncthreads();
#pragma unroll
        for (int kk = 0; kk < 32; kk++) {
            float bv = B_s[kk][tx];
            acc[0] += A_s[ty][kk] * bv;
            acc[1] += A_s[ty + 8][kk] * bv;
            acc[2] += A_s[ty + 16][kk] * bv;
            acc[3] += A_s[ty + 24][kk] * bv;
        }
        __syncthreads();
    }
#pragma unroll
    for (int ri = 0; ri < 4; ri++)
        g_qm[(b0 + ty + 8 * ri) * 256 + j0 + tx] = acc[ri];
}

// =================================================================
// Kernel 4: logits, shuffle-free.  block = (p, 32-k chunk), grid (64,16).
// phase A: 32 X loads batched in regs (MLP 32), base_s[h][k] transposed.
// phase B: warp=q, lane=k, private 256-h tanh reduction.
// =================================================================
__global__ __launch_bounds__(256)
void logits_kernel(const float* __restrict__ X, const float* __restrict__ varfeat,
                   const float* __restrict__ nn_A, const float* __restrict__ nn_B,
                   const float* __restrict__ nn_W)
{
    __shared__ float base_s[256][33];   // [h][k] padded
    __shared__ float qm_s[8 * 256];
    __shared__ float w_s[256];
    __shared__ float vf_s[8][32];

    const int t  = threadIdx.x;
    const int p  = blockIdx.x;
    const int k0 = blockIdx.y * 32;

    for (int i = t; i < 2048; i += 256) qm_s[i] = g_qm[p * 8 * 256 + i];
    w_s[t] = nn_W[t];
    float a_v[8];
#pragma unroll
    for (int v = 0; v < 8; v++) a_v[v] = nn_A[v * 256 + t];
    const float bB = nn_B[t];
    {
        int v = t >> 5, kk = t & 31;
        vf_s[v][kk] = (k0 + kk < NK) ? varfeat[(p * 8 + v) * NK + k0 + kk] : 0.0f;
    }
    __syncthreads();

    // phase A: thread t owns h = t; all 32 X loads issued up front
    float xv[32];
#pragma unroll
    for (int kk = 0; kk < 32; kk++) {
        int kg = k0 + kk;
        xv[kk] = (kg < NK) ? X[(p * NK + kg) * 256 + t] : 0.0f;
    }
#pragma unroll
    for (int kk = 0; kk < 32; kk++) {
        float vf = bB;
#pragma unroll
        for (int v = 0; v < 8; v++) vf += vf_s[v][kk] * a_v[v];
        base_s[t][kk] = xv[kk] + vf;
    }
    __syncthreads();

    // phase B: warp w = q, lane l = k; private 256-h reduction
    {
        const int w = t >> 5, l = t & 31;
        const int kg = k0 + l;
        const float* qmr = qm_s + w * 256;
        float a0 = 0, a1 = 0, a2 = 0, a3 = 0;
#pragma unroll 16
        for (int h = 0; h < 256; h += 4) {
            a0 += w_s[h + 0] * fast_tanh(base_s[h + 0][l] + qmr[h + 0]);
            a1 += w_s[h + 1] * fast_tanh(base_s[h + 1][l] + qmr[h + 1]);
            a2 += w_s[h + 2] * fast_tanh(base_s[h + 2][l] + qmr[h + 2]);
            a3 += w_s[h + 3] * fast_tanh(base_s[h + 3][l] + qmr[h + 3]);
        }
        if (kg < NK) {
            int idx = (p * 8 + w) * NK + kg;
            g_logit[idx] = g_mask[idx] ? -1e30f : (a0 + a1) + (a2 + a3);
        }
    }
}

// =================================================================
// Kernel 5: choose.  chosen_p = -log(sum exp(l - max)) per row.
// =================================================================
__global__ __launch_bounds__(128)
void choose_kernel(float* __restrict__ out_p)
{
    __shared__ float red[128];
    const int r = blockIdx.x, t = threadIdx.x;
    const float* row = g_logit + r * NK;

    float mx = -1e30f;
    for (int k = t; k < NK; k += 128) {
        float raw = row[k];
        if (raw > -1e29f) mx = fmaxf(mx, tanh_acc(raw) * 10.0f);
    }
    red[t] = mx; __syncthreads();
    for (int s = 64; s > 0; s >>= 1) {
        if (t < s) red[t] = fmaxf(red[t], red[t + s]);
        __syncthreads();
    }
    mx = red[0]; __syncthreads();

    float sm = 0.0f;
    for (int k = t; k < NK; k += 128) {
        float raw = row[k];
        if (raw > -1e29f) sm += __expf(tanh_acc(raw) * 10.0f - mx);
    }
    red[t] = sm; __syncthreads();
    for (int s = 64; s > 0; s >>= 1) {
        if (t < s) red[t] += red[t + s];
        __syncthreads();
    }
    if (t == 0) out_p[r] = -logf(red[0]);
}

// =================================================================
extern "C" void kernel_launch(void* const* d_in, const int* in_sizes, int n_in,
                              void* d_out, int out_size)
{
    const float* X       = (const float*)d_in[0];
    const float* Kt      = (const float*)d_in[1];
    const float* Vt      = (const float*)d_in[2];
    const float* query   = (const float*)d_in[3];
    const float* state1  = (const float*)d_in[4];
    const float* state2  = (const float*)d_in[5];
    const float* varfeat = (const float*)d_in[6];
    const void*  mask    = d_in[7];
    const float* nn_Q    = (const float*)d_in[8];
    const float* nn_O    = (const float*)d_in[9];
    const float* nn_A    = (const float*)d_in[10];
    const float* nn_B    = (const float*)d_in[11];
    const float* nn_W    = (const float*)d_in[12];
    const float* W_ih    = (const float*)d_in[13];
    const float* W_hh    = (const float*)d_in[14];
    const float* b_ih    = (const float*)d_in[15];
    const float* b_hh    = (const float*)d_in[16];

    float* out = (float*)d_out;
    float* out_h = out;                       // [512,256]
    float* out_c = out + 512 * 256;           // [512,256]
    float* out_p = out + 2 * 512 * 256;       // [512]

    detect_mask_kernel<<<1, 1024>>>((const unsigned int*)mask);
    normalize_mask_kernel<<<(BATCH * NK + 255) / 256, 256>>>(mask);
    lstm_kernel<<<dim3(16, 8), 256>>>(query, state1, state2, W_ih, W_hh,
                                      b_ih, b_hh, out_h, out_c);
    qproj_kernel<<<dim3(16, 8), 256>>>(out_h, nn_Q);
    glimpse_part_kernel<<<2048, 256>>>(Kt, Vt);
    glimpse_combine_kernel<<<512, 256>>>();
    qm_kernel<<<dim3(16, 8), 256>>>(nn_O);
    logits_kernel<<<dim3(64, 16), 256>>>(X, varfeat, nn_A, nn_B, nn_W);
    choose_kernel<<<512, 128>>>(out_p);
}

// round 7
// speedup vs baseline: 1.4490x; 1.0417x over previous
#include <cuda_runtime.h>
#include <math.h>

#define NPROB  64
#define NRR    8
#define NK     500
#define HDIM   256
#define NHEADS 8
#define HD     32
#define BATCH  512   // NPROB*NRR
#define KQ     125   // NK / 4 k-split for glimpse
#define NSPLIT 4
#define QKS    4     // qproj K-split

// ---------------- scratch (no allocations allowed) ----------------
__device__ float g_qm[BATCH * HDIM];       // glimpse @ nn_O
__device__ float g_Qpart[QKS * NHEADS * BATCH * HD];  // [kq][a][pq][d]
__device__ float g_logit[BATCH * NK];      // masked logits (-1e30 sentinel)
__device__ unsigned char g_mask[BATCH * NK];
__device__ float g_att_part[NSPLIT * NHEADS * NPROB * NRR * HD];
__device__ float2 g_att_ms[NSPLIT * NHEADS * NPROB * NRR];

// single-instruction MUFU.TANH (abs err ~2^-10.6) -- hot path only
__device__ __forceinline__ float fast_tanh(float x) {
    float y;
    asm("tanh.approx.f32 %0, %1;" : "=f"(y) : "f"(x));
    return y;
}
// exact tanh: 1 - 2/(exp(2x)+1)
__device__ __forceinline__ float tanh_acc(float x) {
    float e = __expf(2.0f * x);
    return 1.0f - __fdividef(2.0f, e + 1.0f);
}
__device__ __forceinline__ float sigmoidf_(float x) {
    return 1.0f / (1.0f + __expf(-x));
}

// =================================================================
// Kernel 1: fused LSTM + mask normalize preamble.
// Each of the 128 blocks: (a) detects mask dtype from first 8000
// words (in-bounds for all candidate dtypes), converts its 2000-elem
// slice to bytes; (b) computes its 32b x 32j LSTM tile.
// =================================================================
__global__ __launch_bounds__(256)
void lstm_kernel(const float* __restrict__ query, const float* __restrict__ state1,
                 const float* __restrict__ state2,
                 const float* __restrict__ W_ih, const float* __restrict__ W_hh,
                 const float* __restrict__ b_ih, const float* __restrict__ b_hh,
                 const void* __restrict__ mraw,
                 float* __restrict__ out_h, float* __restrict__ out_c)
{
    __shared__ float A_s[32][33];
    __shared__ float W_s[4][32][33];
    __shared__ int s_i32, s_f32, s_bf16;
    const int t  = threadIdx.x;
    const int tx = t & 31, ty = t >> 5;
    const int b0 = blockIdx.x * 32, j0 = blockIdx.y * 32;
    const int lrow = t >> 3, lk = (t & 7) * 4;

    // ---- mask preamble: detect dtype ----
    if (t == 0) { s_i32 = 1; s_f32 = 1; s_bf16 = 1; }
    __syncthreads();
    {
        const unsigned int* mw = (const unsigned int*)mraw;
        int ok_i32 = 1, ok_f32 = 1, ok_bf16 = 1;
        for (int i = t; i < 8000; i += 256) {
            unsigned int w = mw[i];
            ok_i32  &= (w <= 1u);
            ok_f32  &= (w == 0u || w == 0x3F800000u);
            unsigned int lo = w & 0xFFFFu, hi = w >> 16;
            ok_bf16 &= (lo == 0u || lo == 0x3F80u) && (hi == 0u || hi == 0x3F80u);
        }
        if (!ok_i32)  atomicAnd(&s_i32, 0);
        if (!ok_f32)  atomicAnd(&s_f32, 0);
        if (!ok_bf16) atomicAnd(&s_bf16, 0);
    }
    __syncthreads();
    {
        int mode = 0;
        if (s_i32) mode = 1;
        else if (s_f32) mode = 2;
        else if (s_bf16) mode = 3;
        const int bid = blockIdx.y * 16 + blockIdx.x;     // 0..127
        const int base = bid * 2000;                      // 128*2000 = 256000
        for (int i = t; i < 2000; i += 256) {
            int idx = base + i;
            unsigned char v;
            if (mode == 1)      v = (((const int*)mraw)[idx] != 0);
            else if (mode == 2) v = (((const unsigned int*)mraw)[idx] != 0u);
            else if (mode == 3) v = (((const unsigned short*)mraw)[idx] != 0u);
            else                v = (((const unsigned char*)mraw)[idx] != 0u);
            g_mask[idx] = v;
        }
    }

    // ---- LSTM GEMM ----
    float acc[4][4];
#pragma unroll
    for (int i = 0; i < 4; i++)
#pragma unroll
        for (int j = 0; j < 4; j++) acc[i][j] = 0.0f;

    for (int k0 = 0; k0 < 512; k0 += 32) {
        const float* Asrc = (k0 < 256) ? (query + k0) : (state1 + (k0 - 256));
        const float* Wsrc = (k0 < 256) ? (W_ih + k0)  : (W_hh  + (k0 - 256));
        float4 av = *(const float4*)&Asrc[(b0 + lrow) * 256 + lk];
        A_s[lrow][lk + 0] = av.x; A_s[lrow][lk + 1] = av.y;
        A_s[lrow][lk + 2] = av.z; A_s[lrow][lk + 3] = av.w;
#pragma unroll
        for (int gg = 0; gg < 4; gg++) {
            float4 wv = *(const float4*)&Wsrc[(gg * 256 + j0 + lrow) * 256 + lk];
            W_s[gg][lrow][lk + 0] = wv.x; W_s[gg][lrow][lk + 1] = wv.y;
            W_s[gg][lrow][lk + 2] = wv.z; W_s[gg][lrow][lk + 3] = wv.w;
        }
        __syncthreads();
#pragma unroll
        for (int kk = 0; kk < 32; kk++) {
            float a0 = A_s[ty][kk], a1 = A_s[ty + 8][kk];
            float a2 = A_s[ty + 16][kk], a3 = A_s[ty + 24][kk];
            float w0 = W_s[0][tx][kk], w1 = W_s[1][tx][kk];
            float w2 = W_s[2][tx][kk], w3 = W_s[3][tx][kk];
            acc[0][0] += a0 * w0; acc[0][1] += a0 * w1; acc[0][2] += a0 * w2; acc[0][3] += a0 * w3;
            acc[1][0] += a1 * w0; acc[1][1] += a1 * w1; acc[1][2] += a1 * w2; acc[1][3] += a1 * w3;
            acc[2][0] += a2 * w0; acc[2][1] += a2 * w1; acc[2][2] += a2 * w2; acc[2][3] += a2 * w3;
            acc[3][0] += a3 * w0; acc[3][1] += a3 * w1; acc[3][2] += a3 * w2; acc[3][3] += a3 * w3;
        }
        __syncthreads();
    }

    const int j = j0 + tx;
    const float bias0 = b_ih[j]       + b_hh[j];
    const float bias1 = b_ih[256 + j] + b_hh[256 + j];
    const float bias2 = b_ih[512 + j] + b_hh[512 + j];
    const float bias3 = b_ih[768 + j] + b_hh[768 + j];
#pragma unroll
    for (int ri = 0; ri < 4; ri++) {
        const int b = b0 + ty + 8 * ri;
        float ig = sigmoidf_(acc[ri][0] + bias0);
        float fg = sigmoidf_(acc[ri][1] + bias1);
        float gg = tanh_acc(acc[ri][2] + bias2);
        float og = sigmoidf_(acc[ri][3] + bias3);
        float c  = fg * state2[b * 256 + j] + ig * gg;
        float h  = og * tanh_acc(c);
        out_h[b * 256 + j] = h;
        out_c[b * 256 + j] = c;
    }
}

// =================================================================
// Kernel 1.5: qproj, K-split 4.  grid = (16 r-tiles x 4 kq x 8 heads)
// = 512 blocks.  Thread computes 4 outputs (float4 over d), 64-deep
// serial loop.  Partials summed at glimpse Q-load.
// =================================================================
__global__ __launch_bounds__(256)
void qproj_kernel(const float* __restrict__ h_in, const float* __restrict__ nn_Q)
{
    __shared__ float h_s[32][65];
    const int t  = threadIdx.x;
    const int a  = blockIdx.x & 7;
    const int kq = (blockIdx.x >> 3) & 3;
    const int r0 = (blockIdx.x >> 5) * 32;

    for (int i = t; i < 2048; i += 256) {
        int r = i >> 6, c = i & 63;
        h_s[r][c] = h_in[(r0 + r) * 256 + kq * 64 + c];
    }
    __syncthreads();

    const int rl = t >> 3, d4 = (t & 7) * 4;
    const float* Qp = nn_Q + a * 8192 + (kq * 64) * 32 + d4;
    float ax = 0, ay = 0, az = 0, aw = 0;
#pragma unroll 8
    for (int h = 0; h < 64; h++) {
        float hv = h_s[rl][h];
        float4 qv = *(const float4*)&Qp[h * 32];
        ax += hv * qv.x; ay += hv * qv.y;
        az += hv * qv.z; aw += hv * qv.w;
    }
    float4 res = make_float4(ax, ay, az, aw);
    *(float4*)&g_Qpart[((kq * 8 + a) * 512 + r0 + rl) * 32 + d4] = res;
}

// =================================================================
// Kernel 2: glimpse partials.  block = (quarter, head a, problem p),
// grid 2048.  Q from summed partials; K and V staged through smem.
// =================================================================
__global__ __launch_bounds__(256)
void glimpse_part_kernel(const float* __restrict__ Kt, const float* __restrict__ Vt)
{
    __shared__ __align__(16) float Q_s[8 * 32];
    __shared__ float S_s[8 * 128];
    __shared__ float K_s[64 * 33];

    const int t = threadIdx.x;
    const int quarter = blockIdx.x >> 9;
    const int a = (blockIdx.x >> 6) & 7;
    const int p = blockIdx.x & 63;
    const int kb = (a * 64 + p) * NK * HD;
    const int kbase = quarter * KQ;

    // 1. Q = sum of 4 qproj partials, scaled
    {
        const int qb = (a * 512 + p * 8) * 32 + t;
        float q = g_Qpart[qb] + g_Qpart[qb + 131072]
                + g_Qpart[qb + 262144] + g_Qpart[qb + 393216];
        Q_s[t] = q * 0.17677669529663687f;
    }
    __syncthreads();

    // 2. S = Q K^T (masked), K staged in 64-row chunks (125 keys)
    const int kloc = t & 63, qp = t >> 6;
    const int q0 = qp * 2, q1 = q0 + 1;
#pragma unroll
    for (int c0 = 0; c0 < KQ; c0 += 64) {
        for (int i = t; i < 2048; i += 256) {
            int row = i >> 5, d = i & 31;
            if (c0 + row < KQ)
                K_s[row * 33 + d] = Kt[kb + (kbase + c0 + row) * 32 + d];
        }
        __syncthreads();
        int kl = c0 + kloc;
        if (kl < KQ) {
            int kg = kbase + kl;
            float acc0 = 0, acc1 = 0;
            const float4* Qs4 = (const float4*)Q_s;
#pragma unroll
            for (int d4 = 0; d4 < 8; d4++) {
                float4 qa = Qs4[q0 * 8 + d4];
                float4 qb = Qs4[q1 * 8 + d4];
                int kbs = kloc * 33 + d4 * 4;
                float k0v = K_s[kbs], k1v = K_s[kbs + 1];
                float k2v = K_s[kbs + 2], k3v = K_s[kbs + 3];
                acc0 += k0v * qa.x + k1v * qa.y + k2v * qa.z + k3v * qa.w;
                acc1 += k0v * qb.x + k1v * qb.y + k2v * qb.z + k3v * qb.w;
            }
            S_s[q0 * 128 + kl] = g_mask[(p * 8 + q0) * NK + kg] ? -1e30f : acc0;
            S_s[q1 * 128 + kl] = g_mask[(p * 8 + q1) * NK + kg] ? -1e30f : acc1;
        }
        __syncthreads();
    }

    // 3. partial softmax stats per q (warp w -> q = w); zero pad [125,128)
    {
        const int w = t >> 5, l = t & 31;
        float mx = -1e30f;
        for (int k = l; k < KQ; k += 32) mx = fmaxf(mx, S_s[w * 128 + k]);
#pragma unroll
        for (int o = 16; o >= 1; o >>= 1) mx = fmaxf(mx, __shfl_xor_sync(0xffffffffu, mx, o));
        float sm = 0;
        for (int k = l; k < KQ; k += 32) {
            float e = __expf(S_s[w * 128 + k] - mx);
            S_s[w * 128 + k] = e;
            sm += e;
        }
#pragma unroll
        for (int o = 16; o >= 1; o >>= 1) sm += __shfl_xor_sync(0xffffffffu, sm, o);
        if (l == 0)
            g_att_ms[((quarter * 8 + a) * 64 + p) * 8 + w] = make_float2(mx, sm);
        for (int k = KQ + l; k < 128; k += 32) S_s[w * 128 + k] = 0.0f;
    }

    // 4. partial (unnormalized) x = S V, V staged through smem
    {
        const int q = t >> 5, d = t & 31;
        float a0 = 0, a1 = 0, a2 = 0, a3 = 0;
#pragma unroll
        for (int c0 = 0; c0 < 128; c0 += 64) {
            __syncthreads();
            for (int i = t; i < 2048; i += 256) {
                int row = i >> 5, dd = i & 31;
                K_s[row * 33 + dd] = (c0 + row < KQ)
                    ? Vt[kb + (kbase + c0 + row) * 32 + dd] : 0.0f;
            }
            __syncthreads();
            const float* sp = S_s + q * 128 + c0;
#pragma unroll
            for (int kk = 0; kk < 64; kk += 4) {
                a0 += sp[kk + 0] * K_s[(kk + 0) * 33 + d];
                a1 += sp[kk + 1] * K_s[(kk + 1) * 33 + d];
                a2 += sp[kk + 2] * K_s[(kk + 2) * 33 + d];
                a3 += sp[kk + 3] * K_s[(kk + 3) * 33 + d];
            }
        }
        g_att_part[(((quarter * 8 + a) * 64 + p) * 8 + q) * 32 + d] = (a0 + a1) + (a2 + a3);
    }
}

// =================================================================
// Kernel 3: qm = glimpse @ nn_O with the 4-way split-softmax combine
// fused into the A-tile load.
// =================================================================
__global__ __launch_bounds__(256)
void qm_kernel(const float* __restrict__ nn_O)
{
    __shared__ float A_s[32][33];
    __shared__ float B_s[32][33];
    __shared__ float wn_s[32][8][4];
    const int t = threadIdx.x, tx = t & 31, ty = t >> 5;
    const int b0 = blockIdx.x * 32, j0 = blockIdx.y * 32;

    // prologue: normalized combine weights for (row rloc, head a)
    {
        const int rloc = t >> 3, a = t & 7;
        const int b = b0 + rloc;
        float2 ms[4];
        float m = -1e30f;
#pragma unroll
        for (int i = 0; i < 4; i++) {
            ms[i] = g_att_ms[i * 4096 + a * 512 + b];
            m = fmaxf(m, ms[i].x);
        }
        float w[4], den = 0.0f;
#pragma unroll
        for (int i = 0; i < 4; i++) {
            w[i] = __expf(ms[i].x - m);
            den += ms[i].y * w[i];
        }
        float inv = 1.0f / den;
#pragma unroll
        for (int i = 0; i < 4; i++) wn_s[rloc][a][i] = w[i] * inv;
    }
    __syncthreads();

    float acc[4] = {0, 0, 0, 0};
    for (int k0 = 0; k0 < 256; k0 += 32) {
        const int a = k0 >> 5;
        for (int i = t; i < 1024; i += 256) {
            int r = i >> 5, c = i & 31;
            int b = b0 + r;
            float v = 0.0f;
#pragma unroll
            for (int s = 0; s < 4; s++)
                v += g_att_part[((s * 8 + a) * 512 + b) * 32 + c] * wn_s[r][a][s];
            A_s[r][c] = v;
            B_s[r][c] = nn_O[(k0 + r) * 256 + j0 + c];
        }
        __syncthreads();
#pragma unroll
        for (int kk = 0; kk < 32; kk++) {
            float bv = B_s[kk][tx];
            acc[0] += A_s[ty][kk] * bv;
            acc[1] += A_s[ty + 8][kk] * bv;
            acc[2] += A_s[ty + 16][kk] * bv;
            acc[3] += A_s[ty + 24][kk] * bv;
        }
        __syncthreads();
    }
#pragma unroll
    for (int ri = 0; ri < 4; ri++)
        g_qm[(b0 + ty + 8 * ri) * 256 + j0 + tx] = acc[ri];
}

// =================================================================
// Kernel 4: logits, shuffle-free.  block = (p, 32-k chunk), grid (64,16).
// =================================================================
__global__ __launch_bounds__(256)
void logits_kernel(const float* __restrict__ X, const float* __restrict__ varfeat,
                   const float* __restrict__ nn_A, const float* __restrict__ nn_B,
                   const float* __restrict__ nn_W)
{
    __shared__ float base_s[256][33];   // [h][k] padded
    __shared__ float qm_s[8 * 256];
    __shared__ float w_s[256];
    __shared__ float vf_s[8][32];

    const int t  = threadIdx.x;
    const int p  = blockIdx.x;
    const int k0 = blockIdx.y * 32;

    for (int i = t; i < 2048; i += 256) qm_s[i] = g_qm[p * 8 * 256 + i];
    w_s[t] = nn_W[t];
    float a_v[8];
#pragma unroll
    for (int v = 0; v < 8; v++) a_v[v] = nn_A[v * 256 + t];
    const float bB = nn_B[t];
    {
        int v = t >> 5, kk = t & 31;
        vf_s[v][kk] = (k0 + kk < NK) ? varfeat[(p * 8 + v) * NK + k0 + kk] : 0.0f;
    }
    __syncthreads();

    // phase A: thread t owns h = t; all 32 X loads issued up front
    float xv[32];
#pragma unroll
    for (int kk = 0; kk < 32; kk++) {
        int kg = k0 + kk;
        xv[kk] = (kg < NK) ? X[(p * NK + kg) * 256 + t] : 0.0f;
    }
#pragma unroll
    for (int kk = 0; kk < 32; kk++) {
        float vf = bB;
#pragma unroll
        for (int v = 0; v < 8; v++) vf += vf_s[v][kk] * a_v[v];
        base_s[t][kk] = xv[kk] + vf;
    }
    __syncthreads();

    // phase B: warp w = q, lane l = k; private 256-h reduction
    {
        const int w = t >> 5, l = t & 31;
        const int kg = k0 + l;
        const float* qmr = qm_s + w * 256;
        float a0 = 0, a1 = 0, a2 = 0, a3 = 0;
#pragma unroll 16
        for (int h = 0; h < 256; h += 4) {
            a0 += w_s[h + 0] * fast_tanh(base_s[h + 0][l] + qmr[h + 0]);
            a1 += w_s[h + 1] * fast_tanh(base_s[h + 1][l] + qmr[h + 1]);
            a2 += w_s[h + 2] * fast_tanh(base_s[h + 2][l] + qmr[h + 2]);
            a3 += w_s[h + 3] * fast_tanh(base_s[h + 3][l] + qmr[h + 3]);
        }
        if (kg < NK) {
            int idx = (p * 8 + w) * NK + kg;
            g_logit[idx] = g_mask[idx] ? -1e30f : (a0 + a1) + (a2 + a3);
        }
    }
}

// =================================================================
// Kernel 5: choose.  Online softmax, single pass, shuffle reduce.
// =================================================================
__global__ __launch_bounds__(128)
void choose_kernel(float* __restrict__ out_p)
{
    __shared__ float2 warp_ms[4];
    const int r = blockIdx.x, t = threadIdx.x;
    const float* row = g_logit + r * NK;

    float m = -1e30f, s = 0.0f;
    for (int k = t; k < NK; k += 128) {
        float raw = row[k];
        if (raw > -1e29f) {
            float x = tanh_acc(raw) * 10.0f;
            if (x > m) { s = s * __expf(m - x) + 1.0f; m = x; }
            else        s += __expf(x - m);
        }
    }
#pragma unroll
    for (int o = 16; o >= 1; o >>= 1) {
        float om = __shfl_xor_sync(0xffffffffu, m, o);
        float os = __shfl_xor_sync(0xffffffffu, s, o);
        float M = fmaxf(m, om);
        s = s * __expf(m - M) + os * __expf(om - M);
        m = M;
    }
    if ((t & 31) == 0) warp_ms[t >> 5] = make_float2(m, s);
    __syncthreads();
    if (t == 0) {
        float M = fmaxf(fmaxf(warp_ms[0].x, warp_ms[1].x),
                        fmaxf(warp_ms[2].x, warp_ms[3].x));
        float S = warp_ms[0].y * __expf(warp_ms[0].x - M)
                + warp_ms[1].y * __expf(warp_ms[1].x - M)
                + warp_ms[2].y * __expf(warp_ms[2].x - M)
                + warp_ms[3].y * __expf(warp_ms[3].x - M);
        out_p[r] = -logf(S);
    }
}

// =================================================================
extern "C" void kernel_launch(void* const* d_in, const int* in_sizes, int n_in,
                              void* d_out, int out_size)
{
    const float* X       = (const float*)d_in[0];
    const float* Kt      = (const float*)d_in[1];
    const float* Vt      = (const float*)d_in[2];
    const float* query   = (const float*)d_in[3];
    const float* state1  = (const float*)d_in[4];
    const float* state2  = (const float*)d_in[5];
    const float* varfeat = (const float*)d_in[6];
    const void*  mask    = d_in[7];
    const float* nn_Q    = (const float*)d_in[8];
    const float* nn_O    = (const float*)d_in[9];
    const float* nn_A    = (const float*)d_in[10];
    const float* nn_B    = (const float*)d_in[11];
    const float* nn_W    = (const float*)d_in[12];
    const float* W_ih    = (const float*)d_in[13];
    const float* W_hh    = (const float*)d_in[14];
    const float* b_ih    = (const float*)d_in[15];
    const float* b_hh    = (const float*)d_in[16];

    float* out = (float*)d_out;
    float* out_h = out;                       // [512,256]
    float* out_c = out + 512 * 256;           // [512,256]
    float* out_p = out + 2 * 512 * 256;       // [512]

    lstm_kernel<<<dim3(16, 8), 256>>>(query, state1, state2, W_ih, W_hh,
                                      b_ih, b_hh, mask, out_h, out_c);
    qproj_kernel<<<512, 256>>>(out_h, nn_Q);
    glimpse_part_kernel<<<2048, 256>>>(Kt, Vt);
    qm_kernel<<<dim3(16, 8), 256>>>(nn_O);
    logits_kernel<<<dim3(64, 16), 256>>>(X, varfeat, nn_A, nn_B, nn_W);
    choose_kernel<<<512, 128>>>(out_p);
}